// round 1
// baseline (speedup 1.0000x reference)
#include <cuda_runtime.h>
#include <math.h>

// Problem constants
#define B       64
#define NNODES  1024
#define ROWS    65536        // B * NNODES
#define NBSTRIDE 33792       // observations row stride = N + N*F_IN
#define F_IN    32
#define H       256
#define MIDDIM  1056         // 32 + 4*256
#define ZDIM    512
#define MIN_VAL (-10000000.0f)

// Persistent scratch (BSS, zero-init; no runtime allocation)
__device__ float g_x  [(size_t)ROWS * F_IN];   //   8.4 MB  extracted node features
__device__ float g_agg[(size_t)ROWS * H];      //  67 MB    neighbor-aggregated input
__device__ float g_h  [(size_t)ROWS * H];      //  67 MB    current layer activations
__device__ float g_z  [(size_t)ROWS * ZDIM];   // 134 MB    accumulated xc @ W1

// ---------------------------------------------------------------------------
// Extract x: obs[b, 1024 : 1024+32768] is exactly x[b] row-major. float4 copy.
// grid: 524288/256 blocks
// ---------------------------------------------------------------------------
__global__ void extract_x_kernel(const float* __restrict__ obs) {
    int idx = blockIdx.x * 256 + threadIdx.x;       // float4 index, 524288 total
    int b   = idx >> 13;                            // 8192 float4 per batch row
    int t   = idx & 8191;
    reinterpret_cast<float4*>(g_x)[idx] =
        reinterpret_cast<const float4*>(obs + (size_t)b * NBSTRIDE + NNODES)[t];
}

// ---------------------------------------------------------------------------
// Neighbor aggregation on the 32x32 grid (4-neighborhood, no atomics).
// F = 32 reads g_x, F = 256 reads g_h; always writes g_agg (compact stride F).
// ---------------------------------------------------------------------------
template<int F>
__global__ void agg_kernel() {
    constexpr int C4 = F / 4;
    int idx = blockIdx.x * 256 + threadIdx.x;       // ROWS*C4 total
    int row = idx / C4;
    int c4  = idx - row * C4;
    int b   = row >> 10;
    int n   = row & 1023;
    int r   = n >> 5, c = n & 31;
    const float4* p = reinterpret_cast<const float4*>(F == 32 ? g_x : g_h);
    int base = ((b << 10) * C4) + c4;
    float4 acc = make_float4(0.f, 0.f, 0.f, 0.f);
    if (c > 0)  { float4 v = p[base + (n - 1)  * C4]; acc.x += v.x; acc.y += v.y; acc.z += v.z; acc.w += v.w; }
    if (c < 31) { float4 v = p[base + (n + 1)  * C4]; acc.x += v.x; acc.y += v.y; acc.z += v.z; acc.w += v.w; }
    if (r > 0)  { float4 v = p[base + (n - 32) * C4]; acc.x += v.x; acc.y += v.y; acc.z += v.z; acc.w += v.w; }
    if (r < 31) { float4 v = p[base + (n + 32) * C4]; acc.x += v.x; acc.y += v.y; acc.z += v.z; acc.w += v.w; }
    reinterpret_cast<float4*>(g_agg)[idx] = acc;
}

// ---------------------------------------------------------------------------
// Fused GEMM + bias + LayerNorm + ReLU:  g_h = relu(LN(g_agg @ W + bias))
// Block tile 64x256, 256 threads, 8x8 micro-tile. Warp ty owns rows ty*8..+7,
// lanes hold cols tx+32*jj -> full 256-col row lives inside one warp (LN via shfl).
// grid: ROWS/64 = 1024 blocks.
// ---------------------------------------------------------------------------
template<int K>
__global__ void __launch_bounds__(256, 2)
gemm_ln_kernel(const float* __restrict__ W, const float* __restrict__ bias,
               const float* __restrict__ gamma, const float* __restrict__ beta) {
    __shared__ float As[64][16];
    __shared__ float Wt[16][256];
    const float* A = g_agg;

    int tid = threadIdx.x;
    int tx  = tid & 31, ty = tid >> 5;
    int row0 = blockIdx.x << 6;

    float acc[8][8];
#pragma unroll
    for (int i = 0; i < 8; i++)
#pragma unroll
        for (int j = 0; j < 8; j++) acc[i][j] = 0.f;

    for (int k0 = 0; k0 < K; k0 += 16) {
        // Load A tile 64x16 (one float4 per thread)
        {
            int r = tid >> 2, kq = (tid & 3) << 2;
            *reinterpret_cast<float4*>(&As[r][kq]) =
                *reinterpret_cast<const float4*>(&A[(size_t)(row0 + r) * K + k0 + kq]);
        }
        // Load W tile 16x256 (4 float4 per thread)
#pragma unroll
        for (int i = 0; i < 4; i++) {
            int t4 = tid + 256 * i;                 // 1024 float4 total
            int kk = t4 >> 6, c4 = (t4 & 63) << 2;
            *reinterpret_cast<float4*>(&Wt[kk][c4]) =
                *reinterpret_cast<const float4*>(&W[(size_t)(k0 + kk) * 256 + c4]);
        }
        __syncthreads();
#pragma unroll
        for (int kk = 0; kk < 16; kk++) {
            float a[8], w[8];
#pragma unroll
            for (int ii = 0; ii < 8; ii++) a[ii] = As[ty * 8 + ii][kk];
#pragma unroll
            for (int jj = 0; jj < 8; jj++) w[jj] = Wt[kk][tx + 32 * jj];
#pragma unroll
            for (int ii = 0; ii < 8; ii++)
#pragma unroll
                for (int jj = 0; jj < 8; jj++)
                    acc[ii][jj] = fmaf(a[ii], w[jj], acc[ii][jj]);
        }
        __syncthreads();
    }

    // Epilogue: bias -> LayerNorm(256) -> affine -> ReLU -> store
    float bc[8], gc[8], bec[8];
#pragma unroll
    for (int jj = 0; jj < 8; jj++) {
        int col = tx + 32 * jj;
        bc[jj] = bias[col]; gc[jj] = gamma[col]; bec[jj] = beta[col];
    }
#pragma unroll
    for (int ii = 0; ii < 8; ii++) {
        float s1 = 0.f, s2 = 0.f;
#pragma unroll
        for (int jj = 0; jj < 8; jj++) {
            float zv = acc[ii][jj] + bc[jj];
            acc[ii][jj] = zv;
            s1 += zv;
            s2 = fmaf(zv, zv, s2);
        }
#pragma unroll
        for (int o = 16; o; o >>= 1) {
            s1 += __shfl_xor_sync(0xffffffffu, s1, o);
            s2 += __shfl_xor_sync(0xffffffffu, s2, o);
        }
        float mu   = s1 * (1.f / 256.f);
        float var  = fmaf(-mu, mu, s2 * (1.f / 256.f));
        float rstd = rsqrtf(var + 1e-5f);
        int row = row0 + ty * 8 + ii;
#pragma unroll
        for (int jj = 0; jj < 8; jj++) {
            float hv = fmaxf(fmaf((acc[ii][jj] - mu) * rstd, gc[jj], bec[jj]), 0.f);
            g_h[(size_t)row * 256 + tx + 32 * jj] = hv;
        }
    }
}

// ---------------------------------------------------------------------------
// z accumulate:  g_z[., col0:col0+128] (+)= A @ W1slice   (A = g_x if INIT else g_h)
// INIT also adds b1. Block tile 64x128, 256 threads, 8x4 micro-tile.
// grid: (ROWS/64, 512/128)
// ---------------------------------------------------------------------------
template<int K, bool INIT>
__global__ void __launch_bounds__(256, 2)
gemm_acc_kernel(const float* __restrict__ Wsl, const float* __restrict__ bias) {
    __shared__ float As[64][16];
    __shared__ float Wt[16][128];
    const float* A = INIT ? g_x : g_h;

    int tid = threadIdx.x;
    int tx  = tid & 31, ty = tid >> 5;
    int row0 = blockIdx.x << 6;
    int col0 = blockIdx.y << 7;

    float acc[8][4];
#pragma unroll
    for (int i = 0; i < 8; i++)
#pragma unroll
        for (int j = 0; j < 4; j++) acc[i][j] = 0.f;

    for (int k0 = 0; k0 < K; k0 += 16) {
        {
            int r = tid >> 2, kq = (tid & 3) << 2;
            *reinterpret_cast<float4*>(&As[r][kq]) =
                *reinterpret_cast<const float4*>(&A[(size_t)(row0 + r) * K + k0 + kq]);
        }
#pragma unroll
        for (int i = 0; i < 2; i++) {
            int t4 = tid + 256 * i;                 // 512 float4 total
            int kk = t4 >> 5, c4 = (t4 & 31) << 2;
            *reinterpret_cast<float4*>(&Wt[kk][c4]) =
                *reinterpret_cast<const float4*>(&Wsl[(size_t)(k0 + kk) * 512 + col0 + c4]);
        }
        __syncthreads();
#pragma unroll
        for (int kk = 0; kk < 16; kk++) {
            float a[8], w[4];
#pragma unroll
            for (int ii = 0; ii < 8; ii++) a[ii] = As[ty * 8 + ii][kk];
#pragma unroll
            for (int jj = 0; jj < 4; jj++) w[jj] = Wt[kk][tx + 32 * jj];
#pragma unroll
            for (int ii = 0; ii < 8; ii++)
#pragma unroll
                for (int jj = 0; jj < 4; jj++)
                    acc[ii][jj] = fmaf(a[ii], w[jj], acc[ii][jj]);
        }
        __syncthreads();
    }

#pragma unroll
    for (int ii = 0; ii < 8; ii++) {
        int row = row0 + ty * 8 + ii;
        float* zr = g_z + (size_t)row * 512 + col0;
#pragma unroll
        for (int jj = 0; jj < 4; jj++) {
            int col = tx + 32 * jj;
            if (INIT) zr[col] = acc[ii][jj] + bias[col0 + col];
            else      zr[col] += acc[ii][jj];
        }
    }
}

// ---------------------------------------------------------------------------
// Tail: BN(eval) -> ReLU -> dot(W2) + b2 -> mask. One warp per row.
// grid: ROWS/8 blocks of 256.
// ---------------------------------------------------------------------------
__global__ void final_kernel(const float* __restrict__ obs,
                             const float* __restrict__ bn_g, const float* __restrict__ bn_b,
                             const float* __restrict__ bn_m, const float* __restrict__ bn_v,
                             const float* __restrict__ W2,  const float* __restrict__ b2,
                             float* __restrict__ out) {
    int row  = blockIdx.x * 8 + (threadIdx.x >> 5);
    int lane = threadIdx.x & 31;
    const float* zr = g_z + (size_t)row * 512;
    float s = 0.f;
#pragma unroll
    for (int i = 0; i < 16; i++) {
        int j = lane + 32 * i;
        float v = zr[j];
        v = fmaf((v - bn_m[j]) * rsqrtf(bn_v[j] + 1e-5f), bn_g[j], bn_b[j]);
        s = fmaf(fmaxf(v, 0.f), W2[j], s);
    }
#pragma unroll
    for (int o = 16; o; o >>= 1) s += __shfl_xor_sync(0xffffffffu, s, o);
    if (lane == 0) {
        int b = row >> 10, n = row & 1023;
        out[row] = (obs[(size_t)b * NBSTRIDE + n] != 0.f) ? (s + b2[0]) : MIN_VAL;
    }
}

// ---------------------------------------------------------------------------
// Launch
// ---------------------------------------------------------------------------
extern "C" void kernel_launch(void* const* d_in, const int* in_sizes, int n_in,
                              void* d_out, int out_size) {
    const float* obs  = (const float*)d_in[0];
    const float* W0   = (const float*)d_in[3];
    const float* b0   = (const float*)d_in[4];
    const float* g0   = (const float*)d_in[5];
    const float* be0  = (const float*)d_in[6];
    const float* Ws   = (const float*)d_in[7];
    const float* bs   = (const float*)d_in[8];
    const float* gs   = (const float*)d_in[9];
    const float* bes  = (const float*)d_in[10];
    const float* W1   = (const float*)d_in[11];
    const float* b1   = (const float*)d_in[12];
    const float* bn_g = (const float*)d_in[13];
    const float* bn_b = (const float*)d_in[14];
    const float* bn_m = (const float*)d_in[15];
    const float* bn_v = (const float*)d_in[16];
    const float* W2   = (const float*)d_in[17];
    const float* b2   = (const float*)d_in[18];
    float* out = (float*)d_out;

    // Extract node features (also used for layer-0 aggregation)
    extract_x_kernel<<<(ROWS * F_IN / 4) / 256, 256>>>(obs);

    // z = x @ W1[0:32] + b1
    gemm_acc_kernel<32, true><<<dim3(ROWS / 64, 4), 256>>>(W1, b1);

    // Layer 0: agg(x) -> h = relu(LN(agg@W0 + b0)); z += h @ W1[32:288]
    agg_kernel<32><<<(ROWS * 32 / 4) / 256, 256>>>();
    gemm_ln_kernel<32><<<ROWS / 64, 256>>>(W0, b0, g0, be0);
    gemm_acc_kernel<256, false><<<dim3(ROWS / 64, 4), 256>>>(W1 + (size_t)32 * 512, nullptr);

    // Layers 1..3
    for (int l = 1; l < 4; l++) {
        agg_kernel<256><<<(ROWS * 256 / 4) / 256, 256>>>();
        gemm_ln_kernel<256><<<ROWS / 64, 256>>>(Ws + (size_t)(l - 1) * 256 * 256,
                                                bs + (l - 1) * 256,
                                                gs + (l - 1) * 256,
                                                bes + (l - 1) * 256);
        gemm_acc_kernel<256, false><<<dim3(ROWS / 64, 4), 256>>>(
            W1 + (size_t)(32 + l * 256) * 512, nullptr);
    }

    // Tail
    final_kernel<<<ROWS / 8, 256>>>(obs, bn_g, bn_b, bn_m, bn_v, W2, b2, out);
}

// round 2
// speedup vs baseline: 1.0002x; 1.0002x over previous
#include <cuda_runtime.h>
#include <math.h>

// Problem constants
#define B       64
#define NNODES  1024
#define ROWS    65536        // B * NNODES
#define NBSTRIDE 33792       // observations row stride = N + N*F_IN
#define F_IN    32
#define H       256
#define MIDDIM  1056         // 32 + 4*256
#define ZDIM    512
#define MIN_VAL (-10000000.0f)

// Persistent scratch (BSS, zero-init; no runtime allocation)
__device__ float g_x  [(size_t)ROWS * F_IN];   //   8.4 MB  extracted node features
__device__ float g_agg[(size_t)ROWS * H];      //  67 MB    neighbor-aggregated input
__device__ float g_h  [(size_t)ROWS * H];      //  67 MB    current layer activations
__device__ float g_z  [(size_t)ROWS * ZDIM];   // 134 MB    accumulated xc @ W1

// ---------------------------------------------------------------------------
// Extract x: obs[b, 1024 : 1024+32768] is exactly x[b] row-major. float4 copy.
// grid: 524288/256 blocks
// ---------------------------------------------------------------------------
__global__ void extract_x_kernel(const float* __restrict__ obs) {
    int idx = blockIdx.x * 256 + threadIdx.x;       // float4 index, 524288 total
    int b   = idx >> 13;                            // 8192 float4 per batch row
    int t   = idx & 8191;
    reinterpret_cast<float4*>(g_x)[idx] =
        reinterpret_cast<const float4*>(obs + (size_t)b * NBSTRIDE + NNODES)[t];
}

// ---------------------------------------------------------------------------
// Neighbor aggregation on the 32x32 grid (4-neighborhood, no atomics).
// F = 32 reads g_x, F = 256 reads g_h; always writes g_agg (compact stride F).
// ---------------------------------------------------------------------------
template<int F>
__global__ void agg_kernel() {
    constexpr int C4 = F / 4;
    int idx = blockIdx.x * 256 + threadIdx.x;       // ROWS*C4 total
    int row = idx / C4;
    int c4  = idx - row * C4;
    int b   = row >> 10;
    int n   = row & 1023;
    int r   = n >> 5, c = n & 31;
    const float4* p = reinterpret_cast<const float4*>(F == 32 ? g_x : g_h);
    int base = ((b << 10) * C4) + c4;
    float4 acc = make_float4(0.f, 0.f, 0.f, 0.f);
    if (c > 0)  { float4 v = p[base + (n - 1)  * C4]; acc.x += v.x; acc.y += v.y; acc.z += v.z; acc.w += v.w; }
    if (c < 31) { float4 v = p[base + (n + 1)  * C4]; acc.x += v.x; acc.y += v.y; acc.z += v.z; acc.w += v.w; }
    if (r > 0)  { float4 v = p[base + (n - 32) * C4]; acc.x += v.x; acc.y += v.y; acc.z += v.z; acc.w += v.w; }
    if (r < 31) { float4 v = p[base + (n + 32) * C4]; acc.x += v.x; acc.y += v.y; acc.z += v.z; acc.w += v.w; }
    reinterpret_cast<float4*>(g_agg)[idx] = acc;
}

// ---------------------------------------------------------------------------
// Fused GEMM + bias + LayerNorm + ReLU:  g_h = relu(LN(g_agg @ W + bias))
// Block tile 64x256, 256 threads, 8x8 micro-tile. Warp ty owns rows ty*8..+7,
// lanes hold cols tx+32*jj -> full 256-col row lives inside one warp (LN via shfl).
// grid: ROWS/64 = 1024 blocks.
// ---------------------------------------------------------------------------
template<int K>
__global__ void __launch_bounds__(256, 2)
gemm_ln_kernel(const float* __restrict__ W, const float* __restrict__ bias,
               const float* __restrict__ gamma, const float* __restrict__ beta) {
    __shared__ float As[64][16];
    __shared__ float Wt[16][256];
    const float* A = g_agg;

    int tid = threadIdx.x;
    int tx  = tid & 31, ty = tid >> 5;
    int row0 = blockIdx.x << 6;

    float acc[8][8];
#pragma unroll
    for (int i = 0; i < 8; i++)
#pragma unroll
        for (int j = 0; j < 8; j++) acc[i][j] = 0.f;

    for (int k0 = 0; k0 < K; k0 += 16) {
        // Load A tile 64x16 (one float4 per thread)
        {
            int r = tid >> 2, kq = (tid & 3) << 2;
            *reinterpret_cast<float4*>(&As[r][kq]) =
                *reinterpret_cast<const float4*>(&A[(size_t)(row0 + r) * K + k0 + kq]);
        }
        // Load W tile 16x256 (4 float4 per thread)
#pragma unroll
        for (int i = 0; i < 4; i++) {
            int t4 = tid + 256 * i;                 // 1024 float4 total
            int kk = t4 >> 6, c4 = (t4 & 63) << 2;
            *reinterpret_cast<float4*>(&Wt[kk][c4]) =
                *reinterpret_cast<const float4*>(&W[(size_t)(k0 + kk) * 256 + c4]);
        }
        __syncthreads();
#pragma unroll
        for (int kk = 0; kk < 16; kk++) {
            float a[8], w[8];
#pragma unroll
            for (int ii = 0; ii < 8; ii++) a[ii] = As[ty * 8 + ii][kk];
#pragma unroll
            for (int jj = 0; jj < 8; jj++) w[jj] = Wt[kk][tx + 32 * jj];
#pragma unroll
            for (int ii = 0; ii < 8; ii++)
#pragma unroll
                for (int jj = 0; jj < 8; jj++)
                    acc[ii][jj] = fmaf(a[ii], w[jj], acc[ii][jj]);
        }
        __syncthreads();
    }

    // Epilogue: bias -> LayerNorm(256) -> affine -> ReLU -> store
    float bc[8], gc[8], bec[8];
#pragma unroll
    for (int jj = 0; jj < 8; jj++) {
        int col = tx + 32 * jj;
        bc[jj] = bias[col]; gc[jj] = gamma[col]; bec[jj] = beta[col];
    }
#pragma unroll
    for (int ii = 0; ii < 8; ii++) {
        float s1 = 0.f, s2 = 0.f;
#pragma unroll
        for (int jj = 0; jj < 8; jj++) {
            float zv = acc[ii][jj] + bc[jj];
            acc[ii][jj] = zv;
            s1 += zv;
            s2 = fmaf(zv, zv, s2);
        }
#pragma unroll
        for (int o = 16; o; o >>= 1) {
            s1 += __shfl_xor_sync(0xffffffffu, s1, o);
            s2 += __shfl_xor_sync(0xffffffffu, s2, o);
        }
        float mu   = s1 * (1.f / 256.f);
        float var  = fmaf(-mu, mu, s2 * (1.f / 256.f));
        float rstd = rsqrtf(var + 1e-5f);
        int row = row0 + ty * 8 + ii;
#pragma unroll
        for (int jj = 0; jj < 8; jj++) {
            float hv = fmaxf(fmaf((acc[ii][jj] - mu) * rstd, gc[jj], bec[jj]), 0.f);
            g_h[(size_t)row * 256 + tx + 32 * jj] = hv;
        }
    }
}

// ---------------------------------------------------------------------------
// z accumulate:  g_z[., col0:col0+128] (+)= A @ W1slice   (A = g_x if INIT else g_h)
// INIT also adds b1. Block tile 64x128, 256 threads, 8x4 micro-tile.
// grid: (ROWS/64, 512/128)
// ---------------------------------------------------------------------------
template<int K, bool INIT>
__global__ void __launch_bounds__(256, 2)
gemm_acc_kernel(const float* __restrict__ Wsl, const float* __restrict__ bias) {
    __shared__ float As[64][16];
    __shared__ float Wt[16][128];
    const float* A = INIT ? g_x : g_h;

    int tid = threadIdx.x;
    int tx  = tid & 31, ty = tid >> 5;
    int row0 = blockIdx.x << 6;
    int col0 = blockIdx.y << 7;

    float acc[8][4];
#pragma unroll
    for (int i = 0; i < 8; i++)
#pragma unroll
        for (int j = 0; j < 4; j++) acc[i][j] = 0.f;

    for (int k0 = 0; k0 < K; k0 += 16) {
        {
            int r = tid >> 2, kq = (tid & 3) << 2;
            *reinterpret_cast<float4*>(&As[r][kq]) =
                *reinterpret_cast<const float4*>(&A[(size_t)(row0 + r) * K + k0 + kq]);
        }
#pragma unroll
        for (int i = 0; i < 2; i++) {
            int t4 = tid + 256 * i;                 // 512 float4 total
            int kk = t4 >> 5, c4 = (t4 & 31) << 2;
            *reinterpret_cast<float4*>(&Wt[kk][c4]) =
                *reinterpret_cast<const float4*>(&Wsl[(size_t)(k0 + kk) * 512 + col0 + c4]);
        }
        __syncthreads();
#pragma unroll
        for (int kk = 0; kk < 16; kk++) {
            float a[8], w[4];
#pragma unroll
            for (int ii = 0; ii < 8; ii++) a[ii] = As[ty * 8 + ii][kk];
#pragma unroll
            for (int jj = 0; jj < 4; jj++) w[jj] = Wt[kk][tx + 32 * jj];
#pragma unroll
            for (int ii = 0; ii < 8; ii++)
#pragma unroll
                for (int jj = 0; jj < 4; jj++)
                    acc[ii][jj] = fmaf(a[ii], w[jj], acc[ii][jj]);
        }
        __syncthreads();
    }

#pragma unroll
    for (int ii = 0; ii < 8; ii++) {
        int row = row0 + ty * 8 + ii;
        float* zr = g_z + (size_t)row * 512 + col0;
#pragma unroll
        for (int jj = 0; jj < 4; jj++) {
            int col = tx + 32 * jj;
            if (INIT) zr[col] = acc[ii][jj] + bias[col0 + col];
            else      zr[col] += acc[ii][jj];
        }
    }
}

// ---------------------------------------------------------------------------
// Tail: BN(eval) -> ReLU -> dot(W2) + b2 -> mask. One warp per row.
// grid: ROWS/8 blocks of 256.
// ---------------------------------------------------------------------------
__global__ void final_kernel(const float* __restrict__ obs,
                             const float* __restrict__ bn_g, const float* __restrict__ bn_b,
                             const float* __restrict__ bn_m, const float* __restrict__ bn_v,
                             const float* __restrict__ W2,  const float* __restrict__ b2,
                             float* __restrict__ out) {
    int row  = blockIdx.x * 8 + (threadIdx.x >> 5);
    int lane = threadIdx.x & 31;
    const float* zr = g_z + (size_t)row * 512;
    float s = 0.f;
#pragma unroll
    for (int i = 0; i < 16; i++) {
        int j = lane + 32 * i;
        float v = zr[j];
        v = fmaf((v - bn_m[j]) * rsqrtf(bn_v[j] + 1e-5f), bn_g[j], bn_b[j]);
        s = fmaf(fmaxf(v, 0.f), W2[j], s);
    }
#pragma unroll
    for (int o = 16; o; o >>= 1) s += __shfl_xor_sync(0xffffffffu, s, o);
    if (lane == 0) {
        int b = row >> 10, n = row & 1023;
        out[row] = (obs[(size_t)b * NBSTRIDE + n] != 0.f) ? (s + b2[0]) : MIN_VAL;
    }
}

// ---------------------------------------------------------------------------
// Launch
// ---------------------------------------------------------------------------
extern "C" void kernel_launch(void* const* d_in, const int* in_sizes, int n_in,
                              void* d_out, int out_size) {
    const float* obs  = (const float*)d_in[0];
    const float* W0   = (const float*)d_in[3];
    const float* b0   = (const float*)d_in[4];
    const float* g0   = (const float*)d_in[5];
    const float* be0  = (const float*)d_in[6];
    const float* Ws   = (const float*)d_in[7];
    const float* bs   = (const float*)d_in[8];
    const float* gs   = (const float*)d_in[9];
    const float* bes  = (const float*)d_in[10];
    const float* W1   = (const float*)d_in[11];
    const float* b1   = (const float*)d_in[12];
    const float* bn_g = (const float*)d_in[13];
    const float* bn_b = (const float*)d_in[14];
    const float* bn_m = (const float*)d_in[15];
    const float* bn_v = (const float*)d_in[16];
    const float* W2   = (const float*)d_in[17];
    const float* b2   = (const float*)d_in[18];
    float* out = (float*)d_out;

    // Extract node features (also used for layer-0 aggregation)
    extract_x_kernel<<<(ROWS * F_IN / 4) / 256, 256>>>(obs);

    // z = x @ W1[0:32] + b1
    gemm_acc_kernel<32, true><<<dim3(ROWS / 64, 4), 256>>>(W1, b1);

    // Layer 0: agg(x) -> h = relu(LN(agg@W0 + b0)); z += h @ W1[32:288]
    agg_kernel<32><<<(ROWS * 32 / 4) / 256, 256>>>();
    gemm_ln_kernel<32><<<ROWS / 64, 256>>>(W0, b0, g0, be0);
    gemm_acc_kernel<256, false><<<dim3(ROWS / 64, 4), 256>>>(W1 + (size_t)32 * 512, nullptr);

    // Layers 1..3
    for (int l = 1; l < 4; l++) {
        agg_kernel<256><<<(ROWS * 256 / 4) / 256, 256>>>();
        gemm_ln_kernel<256><<<ROWS / 64, 256>>>(Ws + (size_t)(l - 1) * 256 * 256,
                                                bs + (l - 1) * 256,
                                                gs + (l - 1) * 256,
                                                bes + (l - 1) * 256);
        gemm_acc_kernel<256, false><<<dim3(ROWS / 64, 4), 256>>>(
            W1 + (size_t)(32 + l * 256) * 512, nullptr);
    }

    // Tail
    final_kernel<<<ROWS / 8, 256>>>(obs, bn_g, bn_b, bn_m, bn_v, W2, b2, out);
}

// round 5
// speedup vs baseline: 4.7339x; 4.7331x over previous
#include <cuda_runtime.h>
#include <cuda_bf16.h>

typedef unsigned int u32;
typedef __nv_bfloat16 bf16;

#define ROWS 65536
#define NBSTRIDE 33792
#define MIDB 1056
#define MIN_VAL (-10000000.0f)

// ---------------- persistent scratch (BSS) ----------------
__device__ bf16 g_hc [(size_t)ROWS * MIDB];   // [x | h1 | h2 | h3 | h4]
__device__ bf16 g_agg[(size_t)ROWS * 256];
__device__ bf16 g_zb [(size_t)ROWS * 512];
__device__ bf16 g_w0t[256 * 32];              // W0^T [N=256][K=32]
__device__ bf16 g_wst[3][256 * 256];          // Ws^T [N][K]
__device__ bf16 g_w1t[(size_t)512 * 1056];    // W1^T [N=512][K=1056]

// ---------------- helpers ----------------
__device__ __forceinline__ u32 s2u(const void* p){
    u32 a;
    asm("{ .reg .u64 t; cvta.to.shared.u64 t, %1; cvt.u32.u64 %0, t; }" : "=r"(a) : "l"(p));
    return a;
}
__device__ __forceinline__ void cpa16(u32 dst, const void* src){
    asm volatile("cp.async.cg.shared.global [%0], [%1], 16;" :: "r"(dst), "l"(src));
}
#define CP_COMMIT() asm volatile("cp.async.commit_group;" ::: "memory")
#define CP_WAIT(n)  asm volatile("cp.async.wait_group %0;" :: "n"(n) : "memory")

__device__ __forceinline__ void mma16816(float* c, const u32* a, const u32* b){
    asm volatile("mma.sync.aligned.m16n8k16.row.col.f32.bf16.bf16.f32 "
        "{%0,%1,%2,%3}, {%4,%5,%6,%7}, {%8,%9}, {%0,%1,%2,%3};"
        : "+f"(c[0]), "+f"(c[1]), "+f"(c[2]), "+f"(c[3])
        : "r"(a[0]), "r"(a[1]), "r"(a[2]), "r"(a[3]), "r"(b[0]), "r"(b[1]));
}
__device__ __forceinline__ u32 pk(float a, float b){
    __nv_bfloat162 p = __floats2bfloat162_rn(a, b);
    return *reinterpret_cast<u32*>(&p);
}
__device__ __forceinline__ void addu4(float* a, uint4 u){
    float2 f;
    f = __bfloat1622float2(*reinterpret_cast<__nv_bfloat162*>(&u.x)); a[0]+=f.x; a[1]+=f.y;
    f = __bfloat1622float2(*reinterpret_cast<__nv_bfloat162*>(&u.y)); a[2]+=f.x; a[3]+=f.y;
    f = __bfloat1622float2(*reinterpret_cast<__nv_bfloat162*>(&u.z)); a[4]+=f.x; a[5]+=f.y;
    f = __bfloat1622float2(*reinterpret_cast<__nv_bfloat162*>(&u.w)); a[6]+=f.x; a[7]+=f.y;
}

// ---------------- weight prep (fp32 -> bf16, transposed) ----------------
__global__ void prep_w0(const float* __restrict__ W0){
    int i = blockIdx.x * 256 + threadIdx.x;             // 8192
    int n = i >> 5, k = i & 31;
    g_w0t[i] = __float2bfloat16(W0[k * 256 + n]);
}
__global__ void prep_ws(const float* __restrict__ Ws){
    int i = blockIdx.x * 256 + threadIdx.x;             // 3*65536
    int l = i >> 16, r = i & 65535;
    int n = r >> 8, k = r & 255;
    g_wst[l][n * 256 + k] = __float2bfloat16(Ws[l * 65536 + k * 256 + n]);
}
__global__ void prep_w1(const float* __restrict__ W1){
    int i = blockIdx.x * 256 + threadIdx.x;             // 512*1056
    int n = i / 1056, k = i - n * 1056;
    g_w1t[i] = __float2bfloat16(W1[k * 512 + n]);
}

// ---------------- extract x -> g_hc[:, 0:32] ----------------
__global__ void xcvt(const float* __restrict__ obs){
    int q = blockIdx.x * 256 + threadIdx.x;             // ROWS*4
    int row = q >> 2, j = q & 3;
    int b = row >> 10, n = row & 1023;
    const float4* s = reinterpret_cast<const float4*>(obs + (size_t)b * NBSTRIDE + 1024 + n * 32 + j * 8);
    float4 a = s[0], c = s[1];
    *reinterpret_cast<uint4*>(g_hc + (size_t)row * MIDB + j * 8) =
        make_uint4(pk(a.x, a.y), pk(a.z, a.w), pk(c.x, c.y), pk(c.z, c.w));
}

// ---------------- grid 4-neighbor aggregation ----------------
template<int F>
__global__ void agg_tc(int src_col){
    constexpr int C8 = F / 8;
    int q = blockIdx.x * 256 + threadIdx.x;             // ROWS*C8
    int row = q / C8, c8 = q - row * C8;
    int b = row >> 10, n = row & 1023;
    int r = n >> 5, c = n & 31;
    const char* base = reinterpret_cast<const char*>(g_hc + (size_t)(b << 10) * MIDB + src_col) + c8 * 16;
    float acc[8] = {0,0,0,0,0,0,0,0};
    if (c > 0)  addu4(acc, *reinterpret_cast<const uint4*>(base + (size_t)(n - 1)  * (MIDB * 2)));
    if (c < 31) addu4(acc, *reinterpret_cast<const uint4*>(base + (size_t)(n + 1)  * (MIDB * 2)));
    if (r > 0)  addu4(acc, *reinterpret_cast<const uint4*>(base + (size_t)(n - 32) * (MIDB * 2)));
    if (r < 31) addu4(acc, *reinterpret_cast<const uint4*>(base + (size_t)(n + 32) * (MIDB * 2)));
    *reinterpret_cast<uint4*>(g_agg + (size_t)row * F + c8 * 8) =
        make_uint4(pk(acc[0], acc[1]), pk(acc[2], acc[3]), pk(acc[4], acc[5]), pk(acc[6], acc[7]));
}

// ---------------- HMMA GEMM: out = [relu(LN(.))] (A @ Bt^T + bias) ----------------
// CTA 128x256, 512 threads = 16 warps (4M x 4N), warp tile 32x64 (2 m16 x 8 n8).
// A: [ROWS][KFULL] bf16;  Bt: [N][KFULL] bf16 (K-contiguous). K chunked by 32, cp.async 2-buf.
// SMEM (dynamic): As[2] 128x40 @0/10240, Bs[2] 256x40 @20480/40960, red @61440, musd @65536.
#define SMTOT 66560
template<int KFULL, bool LN>
__global__ void __launch_bounds__(512, 1)
gemm_mma(const bf16* __restrict__ A, const bf16* __restrict__ Bt,
         const float* __restrict__ bias, const float* __restrict__ gamma,
         const float* __restrict__ beta, bf16* __restrict__ outp, int ostride)
{
    extern __shared__ char sm[];
    const u32 sb = s2u(sm);
    const int tid  = threadIdx.x;
    const int lane = tid & 31, wid = tid >> 5;
    const int wm = wid & 3, wn = wid >> 2;
    const int row0  = blockIdx.x << 7;
    const int ncol0 = blockIdx.y << 8;
    Bt   += (size_t)ncol0 * KFULL;
    bias += ncol0;
    outp += ncol0;
    constexpr int NC = KFULL / 32;

    float acc[2][8][4];
#pragma unroll
    for (int mt = 0; mt < 2; mt++)
#pragma unroll
        for (int nt = 0; nt < 8; nt++)
#pragma unroll
            for (int e = 0; e < 4; e++) acc[mt][nt][e] = 0.f;

    // chunk loader: A 128x32 (1 cp/thread), B 256x32 (2 cp/thread)
    auto load_chunk = [&](int kc, int buf){
        {
            int r = tid >> 2, seg = tid & 3;
            cpa16(sb + buf * 10240 + (r * 40 + seg * 8) * 2,
                  A + (size_t)(row0 + r) * KFULL + kc * 32 + seg * 8);
        }
#pragma unroll
        for (int i = 0; i < 2; i++){
            int q = tid + 512 * i;
            int n = q >> 2, seg = q & 3;
            cpa16(sb + 20480 + buf * 20480 + (n * 40 + seg * 8) * 2,
                  Bt + (size_t)n * KFULL + kc * 32 + seg * 8);
        }
        CP_COMMIT();
    };

    load_chunk(0, 0);
    for (int kc = 0; kc < NC; kc++){
        if (kc + 1 < NC){ load_chunk(kc + 1, (kc + 1) & 1); CP_WAIT(1); }
        else            { CP_WAIT(0); }
        __syncthreads();
        const bf16* As = reinterpret_cast<const bf16*>(sm + (kc & 1) * 10240);
        const bf16* Bs = reinterpret_cast<const bf16*>(sm + 20480 + (kc & 1) * 20480);
#pragma unroll
        for (int ks = 0; ks < 2; ks++){
            const int kk = ks * 16 + (lane & 3) * 2;
            u32 a[2][4], b[8][2];
#pragma unroll
            for (int mt = 0; mt < 2; mt++){
                int r = wm * 32 + mt * 16 + (lane >> 2);
                a[mt][0] = *reinterpret_cast<const u32*>(&As[r       * 40 + kk]);
                a[mt][1] = *reinterpret_cast<const u32*>(&As[(r + 8) * 40 + kk]);
                a[mt][2] = *reinterpret_cast<const u32*>(&As[r       * 40 + kk + 8]);
                a[mt][3] = *reinterpret_cast<const u32*>(&As[(r + 8) * 40 + kk + 8]);
            }
#pragma unroll
            for (int nt = 0; nt < 8; nt++){
                int n = wn * 64 + nt * 8 + (lane >> 2);
                b[nt][0] = *reinterpret_cast<const u32*>(&Bs[n * 40 + kk]);
                b[nt][1] = *reinterpret_cast<const u32*>(&Bs[n * 40 + kk + 8]);
            }
#pragma unroll
            for (int mt = 0; mt < 2; mt++)
#pragma unroll
                for (int nt = 0; nt < 8; nt++)
                    mma16816(acc[mt][nt], a[mt], b[nt]);
        }
        __syncthreads();
    }

    const int cbase = wn * 64 + (lane & 3) * 2;

    if (LN){
        // bias + per-row stats. Thread rows: wm*32 + mt*16 + (lane>>2) + 8h.
        float s1[2][2] = {{0,0},{0,0}}, s2[2][2] = {{0,0},{0,0}};
#pragma unroll
        for (int mt = 0; mt < 2; mt++)
#pragma unroll
            for (int nt = 0; nt < 8; nt++){
                int c = cbase + nt * 8;
                float b0 = bias[c], b1v = bias[c + 1];
                float v0 = acc[mt][nt][0] + b0,  v1 = acc[mt][nt][1] + b1v;
                float v2 = acc[mt][nt][2] + b0,  v3 = acc[mt][nt][3] + b1v;
                acc[mt][nt][0] = v0; acc[mt][nt][1] = v1;
                acc[mt][nt][2] = v2; acc[mt][nt][3] = v3;
                s1[mt][0] += v0 + v1; s2[mt][0] = fmaf(v0, v0, fmaf(v1, v1, s2[mt][0]));
                s1[mt][1] += v2 + v3; s2[mt][1] = fmaf(v2, v2, fmaf(v3, v3, s2[mt][1]));
            }
#pragma unroll
        for (int o = 1; o <= 2; o <<= 1)
#pragma unroll
            for (int mt = 0; mt < 2; mt++)
#pragma unroll
                for (int h = 0; h < 2; h++){
                    s1[mt][h] += __shfl_xor_sync(0xffffffffu, s1[mt][h], o);
                    s2[mt][h] += __shfl_xor_sync(0xffffffffu, s2[mt][h], o);
                }
        float2* red = reinterpret_cast<float2*>(sm + 61440);
        if ((lane & 3) == 0){
#pragma unroll
            for (int mt = 0; mt < 2; mt++)
#pragma unroll
                for (int h = 0; h < 2; h++){
                    int r = wm * 32 + mt * 16 + (lane >> 2) + 8 * h;
                    red[r * 4 + wn] = make_float2(s1[mt][h], s2[mt][h]);
                }
        }
        __syncthreads();
        float2* musd = reinterpret_cast<float2*>(sm + 65536);
        if (tid < 128){
            float S1 = 0.f, S2 = 0.f;
#pragma unroll
            for (int w = 0; w < 4; w++){ float2 v = red[tid * 4 + w]; S1 += v.x; S2 += v.y; }
            float mu = S1 * (1.f / 256.f);
            float rstd = rsqrtf(fmaf(-mu, mu, S2 * (1.f / 256.f)) + 1e-5f);
            musd[tid] = make_float2(mu, rstd);
        }
        __syncthreads();
#pragma unroll
        for (int mt = 0; mt < 2; mt++)
#pragma unroll
            for (int h = 0; h < 2; h++){
                int r = wm * 32 + mt * 16 + (lane >> 2) + 8 * h;
                float2 ms = musd[r];
                bf16* orow = outp + (size_t)(row0 + r) * ostride;
#pragma unroll
                for (int nt = 0; nt < 8; nt++){
                    int c = cbase + nt * 8;
                    float v0 = acc[mt][nt][2 * h],     v1 = acc[mt][nt][2 * h + 1];
                    float o0 = fmaxf(fmaf((v0 - ms.x) * ms.y, gamma[c],     beta[c]),     0.f);
                    float o1 = fmaxf(fmaf((v1 - ms.x) * ms.y, gamma[c + 1], beta[c + 1]), 0.f);
                    *reinterpret_cast<u32*>(orow + c) = pk(o0, o1);
                }
            }
    } else {
#pragma unroll
        for (int mt = 0; mt < 2; mt++)
#pragma unroll
            for (int h = 0; h < 2; h++){
                int r = wm * 32 + mt * 16 + (lane >> 2) + 8 * h;
                bf16* orow = outp + (size_t)(row0 + r) * ostride;
#pragma unroll
                for (int nt = 0; nt < 8; nt++){
                    int c = cbase + nt * 8;
                    float v0 = acc[mt][nt][2 * h]     + bias[c];
                    float v1 = acc[mt][nt][2 * h + 1] + bias[c + 1];
                    *reinterpret_cast<u32*>(orow + c) = pk(v0, v1);
                }
            }
    }
}

// ---------------- tail: BN -> ReLU -> dot(W2)+b2 -> mask ----------------
__global__ void final_kernel(const float* __restrict__ obs,
                             const float* __restrict__ bn_g, const float* __restrict__ bn_b,
                             const float* __restrict__ bn_m, const float* __restrict__ bn_v,
                             const float* __restrict__ W2,  const float* __restrict__ b2,
                             float* __restrict__ out) {
    int row  = blockIdx.x * 8 + (threadIdx.x >> 5);
    int lane = threadIdx.x & 31;
    const bf16* zr = g_zb + (size_t)row * 512;
    float s = 0.f;
#pragma unroll
    for (int i = 0; i < 16; i++) {
        int j = lane + 32 * i;
        float v = __bfloat162float(zr[j]);
        v = fmaf((v - bn_m[j]) * rsqrtf(bn_v[j] + 1e-5f), bn_g[j], bn_b[j]);
        s = fmaf(fmaxf(v, 0.f), W2[j], s);
    }
#pragma unroll
    for (int o = 16; o; o >>= 1) s += __shfl_xor_sync(0xffffffffu, s, o);
    if (lane == 0) {
        int b = row >> 10, n = row & 1023;
        out[row] = (obs[(size_t)b * NBSTRIDE + n] != 0.f) ? (s + b2[0]) : MIN_VAL;
    }
}

// ---------------- launch ----------------
extern "C" void kernel_launch(void* const* d_in, const int* in_sizes, int n_in,
                              void* d_out, int out_size) {
    const float* obs  = (const float*)d_in[0];
    const float* W0   = (const float*)d_in[3];
    const float* b0   = (const float*)d_in[4];
    const float* g0   = (const float*)d_in[5];
    const float* be0  = (const float*)d_in[6];
    const float* Ws   = (const float*)d_in[7];
    const float* bs   = (const float*)d_in[8];
    const float* gs   = (const float*)d_in[9];
    const float* bes  = (const float*)d_in[10];
    const float* W1   = (const float*)d_in[11];
    const float* b1   = (const float*)d_in[12];
    const float* bn_g = (const float*)d_in[13];
    const float* bn_b = (const float*)d_in[14];
    const float* bn_m = (const float*)d_in[15];
    const float* bn_v = (const float*)d_in[16];
    const float* W2   = (const float*)d_in[17];
    const float* b2   = (const float*)d_in[18];
    float* out = (float*)d_out;

    static bf16* hc_p = nullptr;  // resolved device pointers for kernel args
    bf16 *hc, *agg, *zb, *w0t, *wst, *w1t;
    cudaGetSymbolAddress((void**)&hc,  g_hc);
    cudaGetSymbolAddress((void**)&agg, g_agg);
    cudaGetSymbolAddress((void**)&zb,  g_zb);
    cudaGetSymbolAddress((void**)&w0t, g_w0t);
    cudaGetSymbolAddress((void**)&wst, g_wst);
    cudaGetSymbolAddress((void**)&w1t, g_w1t);
    (void)hc_p;

    cudaFuncSetAttribute(gemm_mma<32,   true>,  cudaFuncAttributeMaxDynamicSharedMemorySize, SMTOT);
    cudaFuncSetAttribute(gemm_mma<256,  true>,  cudaFuncAttributeMaxDynamicSharedMemorySize, SMTOT);
    cudaFuncSetAttribute(gemm_mma<1056, false>, cudaFuncAttributeMaxDynamicSharedMemorySize, SMTOT);

    prep_w0<<<32,   256>>>(W0);
    prep_ws<<<768,  256>>>(Ws);
    prep_w1<<<2112, 256>>>(W1);
    xcvt<<<1024, 256>>>(obs);

    // Layer 0: agg over x (32-wide) -> h1
    agg_tc<32><<<1024, 256>>>(0);
    gemm_mma<32, true><<<dim3(512, 1), 512, SMTOT>>>(agg, w0t, b0, g0, be0, hc + 32, MIDB);

    // Layers 1..3
    for (int l = 1; l < 4; l++) {
        agg_tc<256><<<8192, 256>>>(32 + (l - 1) * 256);
        gemm_mma<256, true><<<dim3(512, 1), 512, SMTOT>>>(
            agg, wst + (size_t)(l - 1) * 65536,
            bs + (l - 1) * 256, gs + (l - 1) * 256, bes + (l - 1) * 256,
            hc + 32 + l * 256, MIDB);
    }

    // Head: z = hc @ W1 + b1 (N=512 via grid.y=2)
    gemm_mma<1056, false><<<dim3(512, 2), 512, SMTOT>>>(hc, w1t, b1, nullptr, nullptr, zb, 512);

    // Tail
    final_kernel<<<8192, 256>>>(obs, bn_g, bn_b, bn_m, bn_v, W2, b2, out);
}

// round 7
// speedup vs baseline: 4.9463x; 1.0449x over previous
#include <cuda_runtime.h>
#include <cuda_bf16.h>

typedef unsigned int u32;
typedef __nv_bfloat16 bf16;

#define ROWS 65536
#define NBSTRIDE 33792
#define MIDB 1056
#define MIN_VAL (-10000000.0f)

// ---------------- persistent scratch (BSS) ----------------
__device__ bf16 g_hc [(size_t)ROWS * MIDB];   // [x | h1 | h2 | h3 | h4]
__device__ bf16 g_zb [(size_t)ROWS * 512];
__device__ bf16 g_w0t[256 * 32];              // W0^T [N=256][K=32]
__device__ bf16 g_wst[3][256 * 256];          // Ws^T [N][K]
__device__ bf16 g_w1t[(size_t)512 * 1056];    // W1^T [N=512][K=1056]

// ---------------- helpers ----------------
__device__ __forceinline__ u32 s2u(const void* p){
    u32 a;
    asm("{ .reg .u64 t; cvta.to.shared.u64 t, %1; cvt.u32.u64 %0, t; }" : "=r"(a) : "l"(p));
    return a;
}
__device__ __forceinline__ void cpa16(u32 dst, const void* src){
    asm volatile("cp.async.cg.shared.global [%0], [%1], 16;" :: "r"(dst), "l"(src));
}
#define CP_COMMIT() asm volatile("cp.async.commit_group;" ::: "memory")
#define CP_WAIT(n)  asm volatile("cp.async.wait_group %0;" :: "n"(n) : "memory")

__device__ __forceinline__ void mma16816(float* c, const u32* a, const u32* b){
    asm volatile("mma.sync.aligned.m16n8k16.row.col.f32.bf16.bf16.f32 "
        "{%0,%1,%2,%3}, {%4,%5,%6,%7}, {%8,%9}, {%0,%1,%2,%3};"
        : "+f"(c[0]), "+f"(c[1]), "+f"(c[2]), "+f"(c[3])
        : "r"(a[0]), "r"(a[1]), "r"(a[2]), "r"(a[3]), "r"(b[0]), "r"(b[1]));
}
#define LDSM4(r0, r1, r2, r3, addr) \
    asm volatile("ldmatrix.sync.aligned.m8n8.x4.shared.b16 {%0,%1,%2,%3}, [%4];" \
        : "=r"(r0), "=r"(r1), "=r"(r2), "=r"(r3) : "r"(addr))

__device__ __forceinline__ u32 pk(float a, float b){
    __nv_bfloat162 p = __floats2bfloat162_rn(a, b);
    return *reinterpret_cast<u32*>(&p);
}
__device__ __forceinline__ void addu4(float* a, uint4 u){
    float2 f;
    f = __bfloat1622float2(*reinterpret_cast<__nv_bfloat162*>(&u.x)); a[0]+=f.x; a[1]+=f.y;
    f = __bfloat1622float2(*reinterpret_cast<__nv_bfloat162*>(&u.y)); a[2]+=f.x; a[3]+=f.y;
    f = __bfloat1622float2(*reinterpret_cast<__nv_bfloat162*>(&u.z)); a[4]+=f.x; a[5]+=f.y;
    f = __bfloat1622float2(*reinterpret_cast<__nv_bfloat162*>(&u.w)); a[6]+=f.x; a[7]+=f.y;
}

// ---------------- weight prep (fp32 -> bf16, transposed) ----------------
__global__ void prep_w0(const float* __restrict__ W0){
    int i = blockIdx.x * 256 + threadIdx.x;             // 8192
    int n = i >> 5, k = i & 31;
    g_w0t[i] = __float2bfloat16(W0[k * 256 + n]);
}
__global__ void prep_ws(const float* __restrict__ Ws){
    int i = blockIdx.x * 256 + threadIdx.x;             // 3*65536
    int l = i >> 16, r = i & 65535;
    int n = r >> 8, k = r & 255;
    g_wst[l][n * 256 + k] = __float2bfloat16(Ws[l * 65536 + k * 256 + n]);
}
__global__ void prep_w1(const float* __restrict__ W1){
    int i = blockIdx.x * 256 + threadIdx.x;             // 512*1056
    int n = i / 1056, k = i - n * 1056;
    g_w1t[i] = __float2bfloat16(W1[k * 512 + n]);
}

// ---------------- extract x -> g_hc[:, 0:32] ----------------
__global__ void xcvt(const float* __restrict__ obs){
    int q = blockIdx.x * 256 + threadIdx.x;             // ROWS*4
    int row = q >> 2, j = q & 3;
    int b = row >> 10, n = row & 1023;
    const float4* s = reinterpret_cast<const float4*>(obs + (size_t)b * NBSTRIDE + 1024 + n * 32 + j * 8);
    float4 a = s[0], c = s[1];
    *reinterpret_cast<uint4*>(g_hc + (size_t)row * MIDB + j * 8) =
        make_uint4(pk(a.x, a.y), pk(a.z, a.w), pk(c.x, c.y), pk(c.z, c.w));
}

// ---------------- HMMA GEMM (4-stage cp.async, ldmatrix, optional fused grid-agg) ----
// CTA 128x256, 512 threads = 16 warps (4M x 4N), warp tile 32x64.
// A: rows of g_hc (stride MIDB) either direct (head) or 4-neighbor aggregated (layers).
// SMEM: 4 stages x (A 128x40 + B 256x40) bf16 = 4 x 30720B; red @122880; musd @126976.
#define SMTOT 128000
template<int KFULL, bool LN, bool AGG>
__global__ void __launch_bounds__(512, 1)
gemm_mma(const bf16* __restrict__ A, const bf16* __restrict__ Bt,
         const float* __restrict__ bias, const float* __restrict__ gamma,
         const float* __restrict__ beta, bf16* __restrict__ outp, int ostride)
{
    extern __shared__ char sm[];
    const u32 sb = s2u(sm);
    const int tid  = threadIdx.x;
    const int lane = tid & 31, wid = tid >> 5;
    const int wm = wid & 3, wn = wid >> 2;
    const int row0  = blockIdx.x << 7;
    const int ncol0 = blockIdx.y << 8;
    Bt   += (size_t)ncol0 * KFULL;
    bias += ncol0;
    outp += ncol0;
    constexpr int NC = KFULL / 32;

    float acc[2][8][4];
#pragma unroll
    for (int mt = 0; mt < 2; mt++)
#pragma unroll
        for (int nt = 0; nt < 8; nt++)
#pragma unroll
            for (int e = 0; e < 4; e++) acc[mt][nt][e] = 0.f;

    // precomputed for AGG path (one 16B segment per thread)
    const int ar  = tid >> 2, aseg = tid & 3;
    const int arow = row0 + ar;
    const int an = arow & 1023, agr = an >> 5, agc = an & 31;

    auto load_chunk = [&](int kc, int stg){
        const u32 Ab = sb + stg * 30720;
        const u32 Bb = Ab + 10240;
        const u32 adst = Ab + (u32)(ar * 40 + aseg * 8) * 2;
        if (AGG){
            const char* base = reinterpret_cast<const char*>(A) +
                               (size_t)arow * (MIDB * 2) + kc * 64 + aseg * 16;
            float s[8] = {0,0,0,0,0,0,0,0};
            if (agc > 0)  addu4(s, *reinterpret_cast<const uint4*>(base - (MIDB * 2)));
            if (agc < 31) addu4(s, *reinterpret_cast<const uint4*>(base + (MIDB * 2)));
            if (agr > 0)  addu4(s, *reinterpret_cast<const uint4*>(base - 32 * (MIDB * 2)));
            if (agr < 31) addu4(s, *reinterpret_cast<const uint4*>(base + 32 * (MIDB * 2)));
            *reinterpret_cast<uint4*>(sm + (adst - sb)) =
                make_uint4(pk(s[0], s[1]), pk(s[2], s[3]), pk(s[4], s[5]), pk(s[6], s[7]));
        } else {
            cpa16(adst, A + (size_t)arow * MIDB + kc * 32 + aseg * 8);
        }
#pragma unroll
        for (int i = 0; i < 2; i++){
            int q = tid + 512 * i;
            int n = q >> 2, seg = q & 3;
            cpa16(Bb + (u32)(n * 40 + seg * 8) * 2,
                  Bt + (size_t)n * KFULL + kc * 32 + seg * 8);
        }
    };

    // prologue: stages 0..2
#pragma unroll
    for (int p = 0; p < 3; p++){
        if (p < NC) load_chunk(p, p);
        CP_COMMIT();
    }

    for (int kc = 0; kc < NC; kc++){
        CP_WAIT(2);
        __syncthreads();
        if (kc + 3 < NC) load_chunk(kc + 3, (kc + 3) & 3);
        CP_COMMIT();

        const u32 Ab = sb + (kc & 3) * 30720;
        const u32 Bb = Ab + 10240;
#pragma unroll
        for (int ks = 0; ks < 2; ks++){
            u32 a[2][4], b[8][2];
#pragma unroll
            for (int mt = 0; mt < 2; mt++){
                u32 addr = Ab + (u32)(((wm * 32 + mt * 16 + (lane & 7) + ((lane >> 3) & 1) * 8) * 40)
                                      + ks * 16 + (lane >> 4) * 8) * 2;
                LDSM4(a[mt][0], a[mt][1], a[mt][2], a[mt][3], addr);
            }
#pragma unroll
            for (int np = 0; np < 4; np++){
                u32 addr = Bb + (u32)(((wn * 64 + (np * 2 + (lane >> 4)) * 8 + (lane & 7)) * 40)
                                      + ks * 16 + ((lane >> 3) & 1) * 8) * 2;
                LDSM4(b[np * 2][0], b[np * 2][1], b[np * 2 + 1][0], b[np * 2 + 1][1], addr);
            }
#pragma unroll
            for (int mt = 0; mt < 2; mt++)
#pragma unroll
                for (int nt = 0; nt < 8; nt++)
                    mma16816(acc[mt][nt], a[mt], b[nt]);
        }
    }
    __syncthreads();

    const int cbase = wn * 64 + (lane & 3) * 2;

    if (LN){
        float s1[2][2] = {{0,0},{0,0}}, s2[2][2] = {{0,0},{0,0}};
#pragma unroll
        for (int mt = 0; mt < 2; mt++)
#pragma unroll
            for (int nt = 0; nt < 8; nt++){
                int c = cbase + nt * 8;
                float b0 = __ldg(bias + c), b1v = __ldg(bias + c + 1);
                float v0 = acc[mt][nt][0] + b0,  v1 = acc[mt][nt][1] + b1v;
                float v2 = acc[mt][nt][2] + b0,  v3 = acc[mt][nt][3] + b1v;
                acc[mt][nt][0] = v0; acc[mt][nt][1] = v1;
                acc[mt][nt][2] = v2; acc[mt][nt][3] = v3;
                s1[mt][0] += v0 + v1; s2[mt][0] = fmaf(v0, v0, fmaf(v1, v1, s2[mt][0]));
                s1[mt][1] += v2 + v3; s2[mt][1] = fmaf(v2, v2, fmaf(v3, v3, s2[mt][1]));
            }
#pragma unroll
        for (int o = 1; o <= 2; o <<= 1)
#pragma unroll
            for (int mt = 0; mt < 2; mt++)
#pragma unroll
                for (int h = 0; h < 2; h++){
                    s1[mt][h] += __shfl_xor_sync(0xffffffffu, s1[mt][h], o);
                    s2[mt][h] += __shfl_xor_sync(0xffffffffu, s2[mt][h], o);
                }
        float2* red = reinterpret_cast<float2*>(sm + 122880);
        if ((lane & 3) == 0){
#pragma unroll
            for (int mt = 0; mt < 2; mt++)
#pragma unroll
                for (int h = 0; h < 2; h++){
                    int r = wm * 32 + mt * 16 + (lane >> 2) + 8 * h;
                    red[r * 4 + wn] = make_float2(s1[mt][h], s2[mt][h]);
                }
        }
        __syncthreads();
        float2* musd = reinterpret_cast<float2*>(sm + 126976);
        if (tid < 128){
            float S1 = 0.f, S2 = 0.f;
#pragma unroll
            for (int w = 0; w < 4; w++){ float2 v = red[tid * 4 + w]; S1 += v.x; S2 += v.y; }
            float mu = S1 * (1.f / 256.f);
            float rstd = rsqrtf(fmaf(-mu, mu, S2 * (1.f / 256.f)) + 1e-5f);
            musd[tid] = make_float2(mu, rstd);
        }
        __syncthreads();
#pragma unroll
        for (int mt = 0; mt < 2; mt++)
#pragma unroll
            for (int h = 0; h < 2; h++){
                int r = wm * 32 + mt * 16 + (lane >> 2) + 8 * h;
                float2 ms = musd[r];
                bf16* orow = outp + (size_t)(row0 + r) * ostride;
#pragma unroll
                for (int nt = 0; nt < 8; nt++){
                    int c = cbase + nt * 8;
                    float v0 = acc[mt][nt][2 * h],     v1 = acc[mt][nt][2 * h + 1];
                    float o0 = fmaxf(fmaf((v0 - ms.x) * ms.y, __ldg(gamma + c),     __ldg(beta + c)),     0.f);
                    float o1 = fmaxf(fmaf((v1 - ms.x) * ms.y, __ldg(gamma + c + 1), __ldg(beta + c + 1)), 0.f);
                    *reinterpret_cast<u32*>(orow + c) = pk(o0, o1);
                }
            }
    } else {
#pragma unroll
        for (int mt = 0; mt < 2; mt++)
#pragma unroll
            for (int h = 0; h < 2; h++){
                int r = wm * 32 + mt * 16 + (lane >> 2) + 8 * h;
                bf16* orow = outp + (size_t)(row0 + r) * ostride;
#pragma unroll
                for (int nt = 0; nt < 8; nt++){
                    int c = cbase + nt * 8;
                    float v0 = acc[mt][nt][2 * h]     + __ldg(bias + c);
                    float v1 = acc[mt][nt][2 * h + 1] + __ldg(bias + c + 1);
                    *reinterpret_cast<u32*>(orow + c) = pk(v0, v1);
                }
            }
    }
}

// ---------------- tail: BN -> ReLU -> dot(W2)+b2 -> mask ----------------
__global__ void final_kernel(const float* __restrict__ obs,
                             const float* __restrict__ bn_g, const float* __restrict__ bn_b,
                             const float* __restrict__ bn_m, const float* __restrict__ bn_v,
                             const float* __restrict__ W2,  const float* __restrict__ b2,
                             float* __restrict__ out) {
    int row  = blockIdx.x * 8 + (threadIdx.x >> 5);
    int lane = threadIdx.x & 31;
    const bf16* zr = g_zb + (size_t)row * 512;
    float s = 0.f;
#pragma unroll
    for (int i = 0; i < 16; i++) {
        int j = lane + 32 * i;
        float v = __bfloat162float(zr[j]);
        v = fmaf((v - bn_m[j]) * rsqrtf(bn_v[j] + 1e-5f), bn_g[j], bn_b[j]);
        s = fmaf(fmaxf(v, 0.f), W2[j], s);
    }
#pragma unroll
    for (int o = 16; o; o >>= 1) s += __shfl_xor_sync(0xffffffffu, s, o);
    if (lane == 0) {
        int b = row >> 10, n = row & 1023;
        out[row] = (obs[(size_t)b * NBSTRIDE + n] != 0.f) ? (s + b2[0]) : MIN_VAL;
    }
}

// ---------------- launch ----------------
extern "C" void kernel_launch(void* const* d_in, const int* in_sizes, int n_in,
                              void* d_out, int out_size) {
    const float* obs  = (const float*)d_in[0];
    const float* W0   = (const float*)d_in[3];
    const float* b0   = (const float*)d_in[4];
    const float* g0   = (const float*)d_in[5];
    const float* be0  = (const float*)d_in[6];
    const float* Ws   = (const float*)d_in[7];
    const float* bs   = (const float*)d_in[8];
    const float* gs   = (const float*)d_in[9];
    const float* bes  = (const float*)d_in[10];
    const float* W1   = (const float*)d_in[11];
    const float* b1   = (const float*)d_in[12];
    const float* bn_g = (const float*)d_in[13];
    const float* bn_b = (const float*)d_in[14];
    const float* bn_m = (const float*)d_in[15];
    const float* bn_v = (const float*)d_in[16];
    const float* W2   = (const float*)d_in[17];
    const float* b2   = (const float*)d_in[18];
    float* out = (float*)d_out;

    bf16 *hc, *zb, *w0t, *wst, *w1t;
    cudaGetSymbolAddress((void**)&hc,  g_hc);
    cudaGetSymbolAddress((void**)&zb,  g_zb);
    cudaGetSymbolAddress((void**)&w0t, g_w0t);
    cudaGetSymbolAddress((void**)&wst, g_wst);
    cudaGetSymbolAddress((void**)&w1t, g_w1t);

    cudaFuncSetAttribute(gemm_mma<32,   true,  true>,  cudaFuncAttributeMaxDynamicSharedMemorySize, SMTOT);
    cudaFuncSetAttribute(gemm_mma<256,  true,  true>,  cudaFuncAttributeMaxDynamicSharedMemorySize, SMTOT);
    cudaFuncSetAttribute(gemm_mma<1056, false, false>, cudaFuncAttributeMaxDynamicSharedMemorySize, SMTOT);

    prep_w0<<<32,   256>>>(W0);
    prep_ws<<<768,  256>>>(Ws);
    prep_w1<<<2112, 256>>>(W1);
    xcvt<<<1024, 256>>>(obs);

    // Layer 0: h1 = relu(LN(agg(x) @ W0 + b0)), agg fused into A-load
    gemm_mma<32, true, true><<<dim3(512, 1), 512, SMTOT>>>(
        hc, w0t, b0, g0, be0, hc + 32, MIDB);

    // Layers 1..3 (agg fused)
    for (int l = 1; l < 4; l++) {
        gemm_mma<256, true, true><<<dim3(512, 1), 512, SMTOT>>>(
            hc + 32 + (l - 1) * 256, wst + (size_t)(l - 1) * 65536,
            bs + (l - 1) * 256, gs + (l - 1) * 256, bes + (l - 1) * 256,
            hc + 32 + l * 256, MIDB);
    }

    // Head: z = hc @ W1 + b1 (N=512 via grid.y=2)
    gemm_mma<1056, false, false><<<dim3(512, 2), 512, SMTOT>>>(
        hc, w1t, b1, nullptr, nullptr, zb, 512);

    // Tail
    final_kernel<<<8192, 256>>>(obs, bn_g, bn_b, bn_m, bn_v, W2, b2, out);
}

// round 8
// speedup vs baseline: 4.9710x; 1.0050x over previous
#include <cuda_runtime.h>
#include <cuda_bf16.h>

typedef unsigned int u32;
typedef unsigned char u8;
typedef unsigned short u16;
typedef __nv_bfloat16 bf16;

#define ROWS 65536
#define NBSTRIDE 33792
#define MIDB 1056
#define MIN_VAL (-10000000.0f)

// ---------------- persistent scratch (BSS) ----------------
__device__ u8   g_hc [(size_t)ROWS * MIDB];   // fp8 e4m3: [x | h1 | h2 | h3 | h4]
__device__ bf16 g_zb [(size_t)ROWS * 512];
__device__ u8   g_w0t[256 * 32];              // W0^T [N=256][K=32] fp8
__device__ u8   g_wst[3][256 * 256];          // Ws^T fp8
__device__ u8   g_w1t[(size_t)512 * 1056];    // W1^T fp8

// ---------------- helpers ----------------
__device__ __forceinline__ u32 s2u(const void* p){
    u32 a;
    asm("{ .reg .u64 t; cvta.to.shared.u64 t, %1; cvt.u32.u64 %0, t; }" : "=r"(a) : "l"(p));
    return a;
}
__device__ __forceinline__ void cpa16(u32 dst, const void* src){
    asm volatile("cp.async.cg.shared.global [%0], [%1], 16;" :: "r"(dst), "l"(src));
}
#define CP_COMMIT() asm volatile("cp.async.commit_group;" ::: "memory")
#define CP_WAIT(n)  asm volatile("cp.async.wait_group %0;" :: "n"(n) : "memory")

__device__ __forceinline__ void mma_fp8(float* c, const u32* a, const u32* b){
    asm volatile("mma.sync.aligned.m16n8k32.row.col.f32.e4m3.e4m3.f32 "
        "{%0,%1,%2,%3}, {%4,%5,%6,%7}, {%8,%9}, {%0,%1,%2,%3};"
        : "+f"(c[0]), "+f"(c[1]), "+f"(c[2]), "+f"(c[3])
        : "r"(a[0]), "r"(a[1]), "r"(a[2]), "r"(a[3]), "r"(b[0]), "r"(b[1]));
}
#define LDSM4(r0, r1, r2, r3, addr) \
    asm volatile("ldmatrix.sync.aligned.m8n8.x4.shared.b16 {%0,%1,%2,%3}, [%4];" \
        : "=r"(r0), "=r"(r1), "=r"(r2), "=r"(r3) : "r"(addr))

__device__ __forceinline__ u16 pk8(float lo, float hi){   // e4m3 pair, lo in low byte
    u16 t;
    asm("cvt.rn.satfinite.e4m3x2.f32 %0, %1, %2;" : "=h"(t) : "f"(hi), "f"(lo));
    return t;
}
__device__ __forceinline__ u8 cvt1(float v){
    return (u8)(pk8(v, 0.f) & 0xff);
}
__device__ __forceinline__ u32 pkbf(float a, float b){
    __nv_bfloat162 p = __floats2bfloat162_rn(a, b);
    return *reinterpret_cast<u32*>(&p);
}
__device__ __forceinline__ void add_fp8x4(float* a, u32 v){
    u32 f0, f1;
    asm("cvt.rn.f16x2.e4m3x2 %0, %1;" : "=r"(f0) : "h"((u16)(v & 0xffff)));
    asm("cvt.rn.f16x2.e4m3x2 %0, %1;" : "=r"(f1) : "h"((u16)(v >> 16)));
    float2 g0 = __half22float2(*reinterpret_cast<__half2*>(&f0));
    float2 g1 = __half22float2(*reinterpret_cast<__half2*>(&f1));
    a[0] += g0.x; a[1] += g0.y; a[2] += g1.x; a[3] += g1.y;
}
__device__ __forceinline__ void addq(float* a, uint4 u){
    add_fp8x4(a,      u.x); add_fp8x4(a + 4,  u.y);
    add_fp8x4(a + 8,  u.z); add_fp8x4(a + 12, u.w);
}

// ---------------- weight prep (fp32 -> e4m3, transposed) ----------------
__global__ void prep_w0(const float* __restrict__ W0){
    int i = blockIdx.x * 256 + threadIdx.x;             // 8192
    int n = i >> 5, k = i & 31;
    g_w0t[i] = cvt1(W0[k * 256 + n]);
}
__global__ void prep_ws(const float* __restrict__ Ws){
    int i = blockIdx.x * 256 + threadIdx.x;             // 3*65536
    int l = i >> 16, r = i & 65535;
    int n = r >> 8, k = r & 255;
    g_wst[l][n * 256 + k] = cvt1(Ws[l * 65536 + k * 256 + n]);
}
__global__ void prep_w1(const float* __restrict__ W1){
    int i = blockIdx.x * 256 + threadIdx.x;             // 512*1056
    int n = i / 1056, k = i - n * 1056;
    g_w1t[i] = cvt1(W1[k * 512 + n]);
}

// ---------------- extract x -> g_hc[:, 0:32] (fp8) ----------------
__global__ void xcvt(const float* __restrict__ obs){
    int q = blockIdx.x * 256 + threadIdx.x;             // ROWS*4
    int row = q >> 2, j = q & 3;
    int b = row >> 10, n = row & 1023;
    const float4* s = reinterpret_cast<const float4*>(obs + (size_t)b * NBSTRIDE + 1024 + n * 32 + j * 8);
    float4 a = s[0], c = s[1];
    u32 w0 = (u32)pk8(a.x, a.y) | ((u32)pk8(a.z, a.w) << 16);
    u32 w1 = (u32)pk8(c.x, c.y) | ((u32)pk8(c.z, c.w) << 16);
    *reinterpret_cast<uint2*>(g_hc + (size_t)row * MIDB + j * 8) = make_uint2(w0, w1);
}

// ---------------- FP8 MMA GEMM (4-stage cp.async, ldmatrix, optional fused grid-agg) ----
// CTA 128x256, 512 threads = 16 warps (4M x 4N), warp tile 32x64, K chunk = 32 fp8 (one k32 mma).
// SMEM: 4 stages x (A 128x48B + B 256x48B) = 4 x 18432; red @73728; musd @77824. Total 78848.
#define SMTOT 78848
template<int KFULL, bool LN, bool AGG>
__global__ void __launch_bounds__(512, 1)
gemm_mma(const u8* __restrict__ A, const u8* __restrict__ Bt,
         const float* __restrict__ bias, const float* __restrict__ gamma,
         const float* __restrict__ beta, void* __restrict__ outv, int ostride)
{
    extern __shared__ char sm[];
    const u32 sb = s2u(sm);
    const int tid  = threadIdx.x;
    const int lane = tid & 31, wid = tid >> 5;
    const int wm = wid & 3, wn = wid >> 2;
    const int row0  = blockIdx.x << 7;
    const int ncol0 = blockIdx.y << 8;
    Bt   += (size_t)ncol0 * KFULL;
    bias += ncol0;
    constexpr int NC = KFULL / 32;

    float acc[2][8][4];
#pragma unroll
    for (int mt = 0; mt < 2; mt++)
#pragma unroll
        for (int nt = 0; nt < 8; nt++)
#pragma unroll
            for (int e = 0; e < 4; e++) acc[mt][nt][e] = 0.f;

    // A loader geometry: threads 0..255 handle one 16B segment each (128 rows x 2 segs)
    const int ar = (tid & 255) >> 1, aseg = tid & 1;
    const int arow = row0 + ar;
    const int an = arow & 1023, agr = an >> 5, agc = an & 31;

    auto load_chunk = [&](int kc, int stg){
        const u32 stgo = (u32)stg * 18432u;
        if (tid < 256){
            const u32 aoff = stgo + (u32)(ar * 48 + aseg * 16);
            if (AGG){
                const u8* base = A + (size_t)arow * MIDB + kc * 32 + aseg * 16;
                float s[16];
#pragma unroll
                for (int e = 0; e < 16; e++) s[e] = 0.f;
                if (agc > 0)  addq(s, *reinterpret_cast<const uint4*>(base - MIDB));
                if (agc < 31) addq(s, *reinterpret_cast<const uint4*>(base + MIDB));
                if (agr > 0)  addq(s, *reinterpret_cast<const uint4*>(base - 32 * MIDB));
                if (agr < 31) addq(s, *reinterpret_cast<const uint4*>(base + 32 * MIDB));
                u32 w0 = (u32)pk8(s[0],  s[1])  | ((u32)pk8(s[2],  s[3])  << 16);
                u32 w1 = (u32)pk8(s[4],  s[5])  | ((u32)pk8(s[6],  s[7])  << 16);
                u32 w2 = (u32)pk8(s[8],  s[9])  | ((u32)pk8(s[10], s[11]) << 16);
                u32 w3 = (u32)pk8(s[12], s[13]) | ((u32)pk8(s[14], s[15]) << 16);
                *reinterpret_cast<uint4*>(sm + aoff) = make_uint4(w0, w1, w2, w3);
            } else {
                cpa16(sb + aoff, A + (size_t)arow * MIDB + kc * 32 + aseg * 16);
            }
        }
        {   // B tile: 256 rows x 32B, 512 x 16B segments
            int n = tid >> 1, seg = tid & 1;
            cpa16(sb + stgo + 6144u + (u32)(n * 48 + seg * 16),
                  Bt + (size_t)n * KFULL + kc * 32 + seg * 16);
        }
    };

#pragma unroll
    for (int p = 0; p < 3; p++){
        if (p < NC) load_chunk(p, p);
        CP_COMMIT();
    }

    for (int kc = 0; kc < NC; kc++){
        CP_WAIT(2);
        __syncthreads();
        if (kc + 3 < NC) load_chunk(kc + 3, (kc + 3) & 3);
        CP_COMMIT();

        const u32 Ab = sb + (u32)(kc & 3) * 18432u;
        const u32 Bb = Ab + 6144u;
        u32 a[2][4], b[8][2];
#pragma unroll
        for (int mt = 0; mt < 2; mt++){
            u32 addr = Ab + (u32)((wm * 32 + mt * 16 + (lane & 7) + ((lane >> 3) & 1) * 8) * 48
                                  + (lane >> 4) * 16);
            LDSM4(a[mt][0], a[mt][1], a[mt][2], a[mt][3], addr);
        }
#pragma unroll
        for (int np = 0; np < 4; np++){
            u32 addr = Bb + (u32)((wn * 64 + (np * 2 + (lane >> 4)) * 8 + (lane & 7)) * 48
                                  + ((lane >> 3) & 1) * 16);
            LDSM4(b[np * 2][0], b[np * 2][1], b[np * 2 + 1][0], b[np * 2 + 1][1], addr);
        }
#pragma unroll
        for (int mt = 0; mt < 2; mt++)
#pragma unroll
            for (int nt = 0; nt < 8; nt++)
                mma_fp8(acc[mt][nt], a[mt], b[nt]);
    }
    __syncthreads();

    const int cbase = wn * 64 + (lane & 3) * 2;

    if (LN){
        float s1[2][2] = {{0,0},{0,0}}, s2[2][2] = {{0,0},{0,0}};
#pragma unroll
        for (int mt = 0; mt < 2; mt++)
#pragma unroll
            for (int nt = 0; nt < 8; nt++){
                int c = cbase + nt * 8;
                float b0 = __ldg(bias + c), b1v = __ldg(bias + c + 1);
                float v0 = acc[mt][nt][0] + b0,  v1 = acc[mt][nt][1] + b1v;
                float v2 = acc[mt][nt][2] + b0,  v3 = acc[mt][nt][3] + b1v;
                acc[mt][nt][0] = v0; acc[mt][nt][1] = v1;
                acc[mt][nt][2] = v2; acc[mt][nt][3] = v3;
                s1[mt][0] += v0 + v1; s2[mt][0] = fmaf(v0, v0, fmaf(v1, v1, s2[mt][0]));
                s1[mt][1] += v2 + v3; s2[mt][1] = fmaf(v2, v2, fmaf(v3, v3, s2[mt][1]));
            }
#pragma unroll
        for (int o = 1; o <= 2; o <<= 1)
#pragma unroll
            for (int mt = 0; mt < 2; mt++)
#pragma unroll
                for (int h = 0; h < 2; h++){
                    s1[mt][h] += __shfl_xor_sync(0xffffffffu, s1[mt][h], o);
                    s2[mt][h] += __shfl_xor_sync(0xffffffffu, s2[mt][h], o);
                }
        float2* red = reinterpret_cast<float2*>(sm + 73728);
        if ((lane & 3) == 0){
#pragma unroll
            for (int mt = 0; mt < 2; mt++)
#pragma unroll
                for (int h = 0; h < 2; h++){
                    int r = wm * 32 + mt * 16 + (lane >> 2) + 8 * h;
                    red[r * 4 + wn] = make_float2(s1[mt][h], s2[mt][h]);
                }
        }
        __syncthreads();
        float2* musd = reinterpret_cast<float2*>(sm + 77824);
        if (tid < 128){
            float S1 = 0.f, S2 = 0.f;
#pragma unroll
            for (int w = 0; w < 4; w++){ float2 v = red[tid * 4 + w]; S1 += v.x; S2 += v.y; }
            float mu = S1 * (1.f / 256.f);
            float rstd = rsqrtf(fmaf(-mu, mu, S2 * (1.f / 256.f)) + 1e-5f);
            musd[tid] = make_float2(mu, rstd);
        }
        __syncthreads();
        u8* outp = reinterpret_cast<u8*>(outv) + ncol0;
#pragma unroll
        for (int mt = 0; mt < 2; mt++)
#pragma unroll
            for (int h = 0; h < 2; h++){
                int r = wm * 32 + mt * 16 + (lane >> 2) + 8 * h;
                float2 ms = musd[r];
                u8* orow = outp + (size_t)(row0 + r) * ostride;
#pragma unroll
                for (int nt = 0; nt < 8; nt++){
                    int c = cbase + nt * 8;
                    float v0 = acc[mt][nt][2 * h],     v1 = acc[mt][nt][2 * h + 1];
                    float o0 = fmaxf(fmaf((v0 - ms.x) * ms.y, __ldg(gamma + c),     __ldg(beta + c)),     0.f);
                    float o1 = fmaxf(fmaf((v1 - ms.x) * ms.y, __ldg(gamma + c + 1), __ldg(beta + c + 1)), 0.f);
                    *reinterpret_cast<u16*>(orow + c) = pk8(o0, o1);
                }
            }
    } else {
        bf16* outp = reinterpret_cast<bf16*>(outv) + ncol0;
#pragma unroll
        for (int mt = 0; mt < 2; mt++)
#pragma unroll
            for (int h = 0; h < 2; h++){
                int r = wm * 32 + mt * 16 + (lane >> 2) + 8 * h;
                bf16* orow = outp + (size_t)(row0 + r) * ostride;
#pragma unroll
                for (int nt = 0; nt < 8; nt++){
                    int c = cbase + nt * 8;
                    float v0 = acc[mt][nt][2 * h]     + __ldg(bias + c);
                    float v1 = acc[mt][nt][2 * h + 1] + __ldg(bias + c + 1);
                    *reinterpret_cast<u32*>(orow + c) = pkbf(v0, v1);
                }
            }
    }
}

// ---------------- tail: BN -> ReLU -> dot(W2)+b2 -> mask ----------------
__global__ void final_kernel(const float* __restrict__ obs,
                             const float* __restrict__ bn_g, const float* __restrict__ bn_b,
                             const float* __restrict__ bn_m, const float* __restrict__ bn_v,
                             const float* __restrict__ W2,  const float* __restrict__ b2,
                             float* __restrict__ out) {
    int row  = blockIdx.x * 8 + (threadIdx.x >> 5);
    int lane = threadIdx.x & 31;
    const bf16* zr = g_zb + (size_t)row * 512;
    float s = 0.f;
#pragma unroll
    for (int i = 0; i < 16; i++) {
        int j = lane + 32 * i;
        float v = __bfloat162float(zr[j]);
        v = fmaf((v - bn_m[j]) * rsqrtf(bn_v[j] + 1e-5f), bn_g[j], bn_b[j]);
        s = fmaf(fmaxf(v, 0.f), W2[j], s);
    }
#pragma unroll
    for (int o = 16; o; o >>= 1) s += __shfl_xor_sync(0xffffffffu, s, o);
    if (lane == 0) {
        int b = row >> 10, n = row & 1023;
        out[row] = (obs[(size_t)b * NBSTRIDE + n] != 0.f) ? (s + b2[0]) : MIN_VAL;
    }
}

// ---------------- launch ----------------
extern "C" void kernel_launch(void* const* d_in, const int* in_sizes, int n_in,
                              void* d_out, int out_size) {
    const float* obs  = (const float*)d_in[0];
    const float* W0   = (const float*)d_in[3];
    const float* b0   = (const float*)d_in[4];
    const float* g0   = (const float*)d_in[5];
    const float* be0  = (const float*)d_in[6];
    const float* Ws   = (const float*)d_in[7];
    const float* bs   = (const float*)d_in[8];
    const float* gs   = (const float*)d_in[9];
    const float* bes  = (const float*)d_in[10];
    const float* W1   = (const float*)d_in[11];
    const float* b1   = (const float*)d_in[12];
    const float* bn_g = (const float*)d_in[13];
    const float* bn_b = (const float*)d_in[14];
    const float* bn_m = (const float*)d_in[15];
    const float* bn_v = (const float*)d_in[16];
    const float* W2   = (const float*)d_in[17];
    const float* b2   = (const float*)d_in[18];
    float* out = (float*)d_out;

    u8 *hc, *w0t, *wst, *w1t; bf16* zb;
    cudaGetSymbolAddress((void**)&hc,  g_hc);
    cudaGetSymbolAddress((void**)&zb,  g_zb);
    cudaGetSymbolAddress((void**)&w0t, g_w0t);
    cudaGetSymbolAddress((void**)&wst, g_wst);
    cudaGetSymbolAddress((void**)&w1t, g_w1t);

    cudaFuncSetAttribute(gemm_mma<32,   true,  true>,  cudaFuncAttributeMaxDynamicSharedMemorySize, SMTOT);
    cudaFuncSetAttribute(gemm_mma<256,  true,  true>,  cudaFuncAttributeMaxDynamicSharedMemorySize, SMTOT);
    cudaFuncSetAttribute(gemm_mma<1056, false, false>, cudaFuncAttributeMaxDynamicSharedMemorySize, SMTOT);

    prep_w0<<<32,   256>>>(W0);
    prep_ws<<<768,  256>>>(Ws);
    prep_w1<<<2112, 256>>>(W1);
    xcvt<<<1024, 256>>>(obs);

    // Layer 0: h1 = relu(LN(agg(x) @ W0 + b0)), agg fused into A-load
    gemm_mma<32, true, true><<<dim3(512, 1), 512, SMTOT>>>(
        hc, w0t, b0, g0, be0, hc + 32, MIDB);

    // Layers 1..3 (agg fused)
    for (int l = 1; l < 4; l++) {
        gemm_mma<256, true, true><<<dim3(512, 1), 512, SMTOT>>>(
            hc + 32 + (l - 1) * 256, wst + (size_t)(l - 1) * 65536,
            bs + (l - 1) * 256, gs + (l - 1) * 256, bes + (l - 1) * 256,
            hc + 32 + l * 256, MIDB);
    }

    // Head: z = hc @ W1 + b1 (N=512 via grid.y=2)
    gemm_mma<1056, false, false><<<dim3(512, 2), 512, SMTOT>>>(
        hc, w1t, b1, nullptr, nullptr, zb, 512);

    // Tail
    final_kernel<<<8192, 256>>>(obs, bn_g, bn_b, bn_m, bn_v, W2, b2, out);
}

// round 9
// speedup vs baseline: 6.0046x; 1.2079x over previous
#include <cuda_runtime.h>
#include <cuda_bf16.h>
#include <cuda_fp16.h>

typedef unsigned int u32;
typedef unsigned char u8;
typedef unsigned short u16;
typedef __nv_bfloat16 bf16;

#define ROWS 65536
#define NBSTRIDE 33792
#define MIDB 1056
#define MIN_VAL (-10000000.0f)

// ---------------- persistent scratch (BSS) ----------------
__device__ u8    g_hc [(size_t)ROWS * MIDB];   // fp8 e4m3: [x | h1 | h2 | h3 | h4]
__device__ u8    g_w0t[256 * 32];              // W0^T [N=256][K=32] fp8
__device__ u8    g_wst[3][256 * 256];          // Ws^T fp8
__device__ u8    g_w1t[(size_t)512 * 1056];    // W1^T fp8
__device__ float g_part[2 * ROWS];             // head partial dots (per N-half)
__device__ float g_sc[512], g_sh[512];         // folded BN scale/shift

// ---------------- helpers ----------------
__device__ __forceinline__ u32 s2u(const void* p){
    u32 a;
    asm("{ .reg .u64 t; cvta.to.shared.u64 t, %1; cvt.u32.u64 %0, t; }" : "=r"(a) : "l"(p));
    return a;
}
__device__ __forceinline__ void cpa16(u32 dst, const void* src){
    asm volatile("cp.async.cg.shared.global [%0], [%1], 16;" :: "r"(dst), "l"(src));
}
#define CP_COMMIT() asm volatile("cp.async.commit_group;" ::: "memory")
#define CP_WAIT(n)  asm volatile("cp.async.wait_group %0;" :: "n"(n) : "memory")

// fp8 MMA with f16 accumulators: c/d = 2 x .f16x2 regs
__device__ __forceinline__ void mma_fp8_h(u32* c, const u32* a, const u32* b){
    asm volatile("mma.sync.aligned.m16n8k32.row.col.f16.e4m3.e4m3.f16 "
        "{%0,%1}, {%2,%3,%4,%5}, {%6,%7}, {%0,%1};"
        : "+r"(c[0]), "+r"(c[1])
        : "r"(a[0]), "r"(a[1]), "r"(a[2]), "r"(a[3]), "r"(b[0]), "r"(b[1]));
}
#define LDSM4(r0, r1, r2, r3, addr) \
    asm volatile("ldmatrix.sync.aligned.m8n8.x4.shared.b16 {%0,%1,%2,%3}, [%4];" \
        : "=r"(r0), "=r"(r1), "=r"(r2), "=r"(r3) : "r"(addr))

__device__ __forceinline__ u16 pk8(float lo, float hi){   // e4m3 pair, lo in low byte
    u16 t;
    asm("cvt.rn.satfinite.e4m3x2.f32 %0, %1, %2;" : "=h"(t) : "f"(hi), "f"(lo));
    return t;
}
__device__ __forceinline__ u8 cvt1(float v){ return (u8)(pk8(v, 0.f) & 0xff); }
__device__ __forceinline__ void add_fp8x4(float* a, u32 v){
    u32 f0, f1;
    asm("cvt.rn.f16x2.e4m3x2 %0, %1;" : "=r"(f0) : "h"((u16)(v & 0xffff)));
    asm("cvt.rn.f16x2.e4m3x2 %0, %1;" : "=r"(f1) : "h"((u16)(v >> 16)));
    float2 g0 = __half22float2(*reinterpret_cast<__half2*>(&f0));
    float2 g1 = __half22float2(*reinterpret_cast<__half2*>(&f1));
    a[0] += g0.x; a[1] += g0.y; a[2] += g1.x; a[3] += g1.y;
}
__device__ __forceinline__ void addq(float* a, uint4 u){
    add_fp8x4(a,      u.x); add_fp8x4(a + 4,  u.y);
    add_fp8x4(a + 8,  u.z); add_fp8x4(a + 12, u.w);
}
__device__ __forceinline__ float2 h2f(u32 h){
    return __half22float2(*reinterpret_cast<__half2*>(&h));
}

// ---------------- prep kernels ----------------
__global__ void prep_w0(const float* __restrict__ W0){
    int i = blockIdx.x * 256 + threadIdx.x;             // 8192
    int n = i >> 5, k = i & 31;
    g_w0t[i] = cvt1(W0[k * 256 + n]);
}
__global__ void prep_ws(const float* __restrict__ Ws){
    int i = blockIdx.x * 256 + threadIdx.x;             // 3*65536
    int l = i >> 16, r = i & 65535;
    int n = r >> 8, k = r & 255;
    g_wst[l][n * 256 + k] = cvt1(Ws[l * 65536 + k * 256 + n]);
}
__global__ void prep_w1(const float* __restrict__ W1){
    int i = blockIdx.x * 256 + threadIdx.x;             // 512*1056
    int n = i / 1056, k = i - n * 1056;
    g_w1t[i] = cvt1(W1[k * 512 + n]);
}
__global__ void prep_bn(const float* __restrict__ bn_g, const float* __restrict__ bn_b,
                        const float* __restrict__ bn_m, const float* __restrict__ bn_v){
    int i = blockIdx.x * 256 + threadIdx.x;             // 512
    float sc = bn_g[i] * rsqrtf(bn_v[i] + 1e-5f);
    g_sc[i] = sc;
    g_sh[i] = bn_b[i] - bn_m[i] * sc;
}
__global__ void xcvt(const float* __restrict__ obs){
    int q = blockIdx.x * 256 + threadIdx.x;             // ROWS*4
    int row = q >> 2, j = q & 3;
    int b = row >> 10, n = row & 1023;
    const float4* s = reinterpret_cast<const float4*>(obs + (size_t)b * NBSTRIDE + 1024 + n * 32 + j * 8);
    float4 a = s[0], c = s[1];
    u32 w0 = (u32)pk8(a.x, a.y) | ((u32)pk8(a.z, a.w) << 16);
    u32 w1 = (u32)pk8(c.x, c.y) | ((u32)pk8(c.z, c.w) << 16);
    *reinterpret_cast<uint2*>(g_hc + (size_t)row * MIDB + j * 8) = make_uint2(w0, w1);
}

// ---------------- FP8 MMA GEMM, 64x256 CTA, 256 thr, occupancy 2 ----------------
// 8 warps: wm = wid&1 (2 M-tiles of 32), wn = wid>>1 (4 N-tiles of 64). f16 accumulators.
// SMEM/stage: A 64x48B @0, B 256x48B @3072 -> 15360; 4 stages = 61440; red @61440; musd @63488.
#define SMTOT 64000
template<int KFULL, bool LN, bool AGG>
__global__ void __launch_bounds__(256, 2)
gemm_mma(const u8* __restrict__ A, const u8* __restrict__ Bt,
         const float* __restrict__ bias, const float* __restrict__ gamma,
         const float* __restrict__ beta, u8* __restrict__ outp, int ostride)
{
    extern __shared__ char sm[];
    const u32 sb = s2u(sm);
    const int tid  = threadIdx.x;
    const int lane = tid & 31, wid = tid >> 5;
    const int wm = wid & 1, wn = wid >> 1;
    const int row0  = blockIdx.x << 6;
    const int ncol0 = blockIdx.y << 8;
    Bt += (size_t)ncol0 * KFULL;
    constexpr int NC = KFULL / 32;

    u32 acc[2][8][2];
#pragma unroll
    for (int mt = 0; mt < 2; mt++)
#pragma unroll
        for (int nt = 0; nt < 8; nt++){ acc[mt][nt][0] = 0u; acc[mt][nt][1] = 0u; }

    // A loader: threads 0..127 handle one 16B segment (64 rows x 2 segs)
    const int ar = tid >> 1, aseg = tid & 1;
    const int arow = row0 + ar;
    const int an = arow & 1023, agr = an >> 5, agc = an & 31;

    auto load_chunk = [&](int kc, int stg){
        const u32 stgo = (u32)stg * 15360u;
        if (tid < 128){
            const u32 aoff = stgo + (u32)(ar * 48 + aseg * 16);
            if (AGG){
                const u8* base = A + (size_t)arow * MIDB + kc * 32 + aseg * 16;
                float s[16];
#pragma unroll
                for (int e = 0; e < 16; e++) s[e] = 0.f;
                if (agc > 0)  addq(s, *reinterpret_cast<const uint4*>(base - MIDB));
                if (agc < 31) addq(s, *reinterpret_cast<const uint4*>(base + MIDB));
                if (agr > 0)  addq(s, *reinterpret_cast<const uint4*>(base - 32 * MIDB));
                if (agr < 31) addq(s, *reinterpret_cast<const uint4*>(base + 32 * MIDB));
                u32 w0 = (u32)pk8(s[0],  s[1])  | ((u32)pk8(s[2],  s[3])  << 16);
                u32 w1 = (u32)pk8(s[4],  s[5])  | ((u32)pk8(s[6],  s[7])  << 16);
                u32 w2 = (u32)pk8(s[8],  s[9])  | ((u32)pk8(s[10], s[11]) << 16);
                u32 w3 = (u32)pk8(s[12], s[13]) | ((u32)pk8(s[14], s[15]) << 16);
                *reinterpret_cast<uint4*>(sm + aoff) = make_uint4(w0, w1, w2, w3);
            } else {
                cpa16(sb + aoff, A + (size_t)arow * MIDB + kc * 32 + aseg * 16);
            }
        }
#pragma unroll
        for (int i = 0; i < 2; i++){   // B: 256 rows x 2 segs = 512 segments
            int q = tid + 256 * i;
            int n = q >> 1, seg = q & 1;
            cpa16(sb + stgo + 3072u + (u32)(n * 48 + seg * 16),
                  Bt + (size_t)n * KFULL + kc * 32 + seg * 16);
        }
    };

#pragma unroll
    for (int p = 0; p < 3; p++){
        if (p < NC) load_chunk(p, p);
        CP_COMMIT();
    }

    for (int kc = 0; kc < NC; kc++){
        CP_WAIT(2);
        __syncthreads();
        if (kc + 3 < NC) load_chunk(kc + 3, (kc + 3) & 3);
        CP_COMMIT();

        const u32 Ab = sb + (u32)(kc & 3) * 15360u;
        const u32 Bb = Ab + 3072u;
        u32 a[2][4], b[8][2];
#pragma unroll
        for (int mt = 0; mt < 2; mt++){
            u32 addr = Ab + (u32)((wm * 32 + mt * 16 + (lane & 7) + ((lane >> 3) & 1) * 8) * 48
                                  + (lane >> 4) * 16);
            LDSM4(a[mt][0], a[mt][1], a[mt][2], a[mt][3], addr);
        }
#pragma unroll
        for (int np = 0; np < 4; np++){
            u32 addr = Bb + (u32)((wn * 64 + (np * 2 + (lane >> 4)) * 8 + (lane & 7)) * 48
                                  + ((lane >> 3) & 1) * 16);
            LDSM4(b[np * 2][0], b[np * 2][1], b[np * 2 + 1][0], b[np * 2 + 1][1], addr);
        }
#pragma unroll
        for (int mt = 0; mt < 2; mt++)
#pragma unroll
            for (int nt = 0; nt < 8; nt++)
                mma_fp8_h(acc[mt][nt], a[mt], b[nt]);
    }
    __syncthreads();

    const int cbase = wn * 64 + (lane & 3) * 2;

    if (LN){
        // unpack f16 acc -> fp32, add bias, LN over 256 cols (4 wn-warps), ReLU, fp8 store
        float vf[2][8][4];
        float s1[2][2] = {{0,0},{0,0}}, s2[2][2] = {{0,0},{0,0}};
#pragma unroll
        for (int mt = 0; mt < 2; mt++)
#pragma unroll
            for (int nt = 0; nt < 8; nt++){
                int c = cbase + nt * 8;
                float b0 = __ldg(bias + c), b1v = __ldg(bias + c + 1);
                float2 p0 = h2f(acc[mt][nt][0]);   // row h=0
                float2 p1 = h2f(acc[mt][nt][1]);   // row h=1
                float v0 = p0.x + b0, v1 = p0.y + b1v;
                float v2 = p1.x + b0, v3 = p1.y + b1v;
                vf[mt][nt][0] = v0; vf[mt][nt][1] = v1;
                vf[mt][nt][2] = v2; vf[mt][nt][3] = v3;
                s1[mt][0] += v0 + v1; s2[mt][0] = fmaf(v0, v0, fmaf(v1, v1, s2[mt][0]));
                s1[mt][1] += v2 + v3; s2[mt][1] = fmaf(v2, v2, fmaf(v3, v3, s2[mt][1]));
            }
#pragma unroll
        for (int o = 1; o <= 2; o <<= 1)
#pragma unroll
            for (int mt = 0; mt < 2; mt++)
#pragma unroll
                for (int h = 0; h < 2; h++){
                    s1[mt][h] += __shfl_xor_sync(0xffffffffu, s1[mt][h], o);
                    s2[mt][h] += __shfl_xor_sync(0xffffffffu, s2[mt][h], o);
                }
        float2* red = reinterpret_cast<float2*>(sm + 61440);
        if ((lane & 3) == 0){
#pragma unroll
            for (int mt = 0; mt < 2; mt++)
#pragma unroll
                for (int h = 0; h < 2; h++){
                    int r = wm * 32 + mt * 16 + (lane >> 2) + 8 * h;
                    red[r * 4 + wn] = make_float2(s1[mt][h], s2[mt][h]);
                }
        }
        __syncthreads();
        float2* musd = reinterpret_cast<float2*>(sm + 63488);
        if (tid < 64){
            float S1 = 0.f, S2 = 0.f;
#pragma unroll
            for (int w = 0; w < 4; w++){ float2 v = red[tid * 4 + w]; S1 += v.x; S2 += v.y; }
            float mu = S1 * (1.f / 256.f);
            float rstd = rsqrtf(fmaf(-mu, mu, S2 * (1.f / 256.f)) + 1e-5f);
            musd[tid] = make_float2(mu, rstd);
        }
        __syncthreads();
#pragma unroll
        for (int mt = 0; mt < 2; mt++)
#pragma unroll
            for (int h = 0; h < 2; h++){
                int r = wm * 32 + mt * 16 + (lane >> 2) + 8 * h;
                float2 ms = musd[r];
                u8* orow = outp + (size_t)(row0 + r) * ostride;
#pragma unroll
                for (int nt = 0; nt < 8; nt++){
                    int c = cbase + nt * 8;
                    float v0 = vf[mt][nt][2 * h], v1 = vf[mt][nt][2 * h + 1];
                    float o0 = fmaxf(fmaf((v0 - ms.x) * ms.y, __ldg(gamma + c),     __ldg(beta + c)),     0.f);
                    float o1 = fmaxf(fmaf((v1 - ms.x) * ms.y, __ldg(gamma + c + 1), __ldg(beta + c + 1)), 0.f);
                    *reinterpret_cast<u16*>(orow + c) = pk8(o0, o1);
                }
            }
    } else {
        // HEAD: fused bias -> BN -> ReLU -> dot(W2 slice) -> per-row partial to g_part
        const float* b1p = bias;                // b1
        float* part = reinterpret_cast<float*>(sm + 61440);   // [64][4]
#pragma unroll
        for (int mt = 0; mt < 2; mt++)
#pragma unroll
            for (int h = 0; h < 2; h++){
                int r = wm * 32 + mt * 16 + (lane >> 2) + 8 * h;
                float s = 0.f;
#pragma unroll
                for (int nt = 0; nt < 8; nt++){
                    int c  = cbase + nt * 8;
                    int gc = ncol0 + c;
                    float2 p = (h == 0) ? h2f(acc[mt][nt][0]) : h2f(acc[mt][nt][1]);
                    float v0 = p.x + __ldg(b1p + gc);
                    float v1 = p.y + __ldg(b1p + gc + 1);
                    float t0 = fmaxf(fmaf(v0, g_sc[gc],     g_sh[gc]),     0.f);
                    float t1 = fmaxf(fmaf(v1, g_sc[gc + 1], g_sh[gc + 1]), 0.f);
                    s = fmaf(t0, __ldg(gamma + gc), s);      // gamma = W2
                    s = fmaf(t1, __ldg(gamma + gc + 1), s);
                }
                s += __shfl_xor_sync(0xffffffffu, s, 1);
                s += __shfl_xor_sync(0xffffffffu, s, 2);
                if ((lane & 3) == 0) part[r * 4 + wn] = s;
            }
        __syncthreads();
        if (tid < 64){
            float S = part[tid * 4] + part[tid * 4 + 1] + part[tid * 4 + 2] + part[tid * 4 + 3];
            g_part[(size_t)blockIdx.y * ROWS + row0 + tid] = S;
        }
    }
}

// ---------------- tail: combine partials, +b2, mask ----------------
__global__ void mask_kernel(const float* __restrict__ obs, const float* __restrict__ b2,
                            float* __restrict__ out){
    int idx = blockIdx.x * 256 + threadIdx.x;           // 65536
    int b = idx >> 10, n = idx & 1023;
    float y = g_part[idx] + g_part[ROWS + idx] + b2[0];
    out[idx] = (obs[(size_t)b * NBSTRIDE + n] != 0.f) ? y : MIN_VAL;
}

// ---------------- launch ----------------
extern "C" void kernel_launch(void* const* d_in, const int* in_sizes, int n_in,
                              void* d_out, int out_size) {
    const float* obs  = (const float*)d_in[0];
    const float* W0   = (const float*)d_in[3];
    const float* b0   = (const float*)d_in[4];
    const float* g0   = (const float*)d_in[5];
    const float* be0  = (const float*)d_in[6];
    const float* Ws   = (const float*)d_in[7];
    const float* bs   = (const float*)d_in[8];
    const float* gs   = (const float*)d_in[9];
    const float* bes  = (const float*)d_in[10];
    const float* W1   = (const float*)d_in[11];
    const float* b1   = (const float*)d_in[12];
    const float* bn_g = (const float*)d_in[13];
    const float* bn_b = (const float*)d_in[14];
    const float* bn_m = (const float*)d_in[15];
    const float* bn_v = (const float*)d_in[16];
    const float* W2   = (const float*)d_in[17];
    const float* b2   = (const float*)d_in[18];
    float* out = (float*)d_out;

    u8 *hc, *w0t, *wst, *w1t;
    cudaGetSymbolAddress((void**)&hc,  g_hc);
    cudaGetSymbolAddress((void**)&w0t, g_w0t);
    cudaGetSymbolAddress((void**)&wst, g_wst);
    cudaGetSymbolAddress((void**)&w1t, g_w1t);

    cudaFuncSetAttribute(gemm_mma<32,   true,  true>,  cudaFuncAttributeMaxDynamicSharedMemorySize, SMTOT);
    cudaFuncSetAttribute(gemm_mma<256,  true,  true>,  cudaFuncAttributeMaxDynamicSharedMemorySize, SMTOT);
    cudaFuncSetAttribute(gemm_mma<1056, false, false>, cudaFuncAttributeMaxDynamicSharedMemorySize, SMTOT);

    prep_w0<<<32,   256>>>(W0);
    prep_ws<<<768,  256>>>(Ws);
    prep_w1<<<2112, 256>>>(W1);
    prep_bn<<<2,    256>>>(bn_g, bn_b, bn_m, bn_v);
    xcvt<<<1024, 256>>>(obs);

    // Layer 0: h1 = relu(LN(agg(x) @ W0 + b0)), agg fused into A-load
    gemm_mma<32, true, true><<<dim3(1024, 1), 256, SMTOT>>>(
        hc, w0t, b0, g0, be0, hc + 32, MIDB);

    // Layers 1..3 (agg fused)
    for (int l = 1; l < 4; l++) {
        gemm_mma<256, true, true><<<dim3(1024, 1), 256, SMTOT>>>(
            hc + 32 + (l - 1) * 256, wst + (size_t)(l - 1) * 65536,
            bs + (l - 1) * 256, gs + (l - 1) * 256, bes + (l - 1) * 256,
            hc + 32 + l * 256, MIDB);
    }

    // Head: fused GEMM + BN + ReLU + W2-dot -> g_part (N=512 via grid.y=2; gamma carries W2)
    gemm_mma<1056, false, false><<<dim3(1024, 2), 256, SMTOT>>>(
        hc, w1t, b1, W2, nullptr, nullptr, 0);

    // Tail: combine partials + mask
    mask_kernel<<<256, 256>>>(obs, b2, out);
}

// round 10
// speedup vs baseline: 6.5688x; 1.0940x over previous
#include <cuda_runtime.h>
#include <cuda_bf16.h>
#include <cuda_fp16.h>

typedef unsigned int u32;
typedef unsigned char u8;
typedef unsigned short u16;

#define ROWS 65536
#define NBSTRIDE 33792
#define MIDB 1088              // padded concat stride (1056 data + 32 zeros)
#define MIN_VAL (-10000000.0f)
#define GRID_P 304             // persistent CTAs (152 SM x occ2)

// ---------------- persistent scratch (BSS, zero-init) ----------------
__device__ u8    g_hc [(size_t)ROWS * MIDB];   // fp8: [x(32) | h1..h4(256 ea) | zeros(32)]
__device__ u8    g_w0t[256 * 64];              // W0^T [N=256][K=64], k>=32 zero
__device__ u8    g_wst[3][256 * 256];          // Ws^T fp8
__device__ u8    g_w1t[(size_t)512 * 1088];    // W1^T fp8, k>=1056 zero
__device__ float g_part[2 * ROWS];             // head partial dots per N-half
__device__ float g_sc[512], g_sh[512];         // folded BN scale/shift
__device__ u32   g_ctr[8];                     // dynamic tile counters

// ---------------- helpers ----------------
__device__ __forceinline__ u32 s2u(const void* p){
    u32 a;
    asm("{ .reg .u64 t; cvta.to.shared.u64 t, %1; cvt.u32.u64 %0, t; }" : "=r"(a) : "l"(p));
    return a;
}
__device__ __forceinline__ void cpa16(u32 dst, const void* src){
    asm volatile("cp.async.cg.shared.global [%0], [%1], 16;" :: "r"(dst), "l"(src));
}
#define CP_COMMIT() asm volatile("cp.async.commit_group;" ::: "memory")
#define CP_WAIT(n)  asm volatile("cp.async.wait_group %0;" :: "n"(n) : "memory")

__device__ __forceinline__ void mma_fp8_h(u32* c, const u32* a, const u32* b){
    asm volatile("mma.sync.aligned.m16n8k32.row.col.f16.e4m3.e4m3.f16 "
        "{%0,%1}, {%2,%3,%4,%5}, {%6,%7}, {%0,%1};"
        : "+r"(c[0]), "+r"(c[1])
        : "r"(a[0]), "r"(a[1]), "r"(a[2]), "r"(a[3]), "r"(b[0]), "r"(b[1]));
}
#define LDSM4(r0, r1, r2, r3, addr) \
    asm volatile("ldmatrix.sync.aligned.m8n8.x4.shared.b16 {%0,%1,%2,%3}, [%4];" \
        : "=r"(r0), "=r"(r1), "=r"(r2), "=r"(r3) : "r"(addr))

__device__ __forceinline__ u16 pk8(float lo, float hi){
    u16 t;
    asm("cvt.rn.satfinite.e4m3x2.f32 %0, %1, %2;" : "=h"(t) : "f"(hi), "f"(lo));
    return t;
}
__device__ __forceinline__ u8 cvt1(float v){ return (u8)(pk8(v, 0.f) & 0xff); }
__device__ __forceinline__ void add_fp8x4(float* a, u32 v){
    u32 f0, f1;
    asm("cvt.rn.f16x2.e4m3x2 %0, %1;" : "=r"(f0) : "h"((u16)(v & 0xffff)));
    asm("cvt.rn.f16x2.e4m3x2 %0, %1;" : "=r"(f1) : "h"((u16)(v >> 16)));
    float2 g0 = __half22float2(*reinterpret_cast<__half2*>(&f0));
    float2 g1 = __half22float2(*reinterpret_cast<__half2*>(&f1));
    a[0] += g0.x; a[1] += g0.y; a[2] += g1.x; a[3] += g1.y;
}
__device__ __forceinline__ void addq(float* a, uint4 u){
    add_fp8x4(a,      u.x); add_fp8x4(a + 4,  u.y);
    add_fp8x4(a + 8,  u.z); add_fp8x4(a + 12, u.w);
}
__device__ __forceinline__ float2 h2f(u32 h){
    return __half22float2(*reinterpret_cast<__half2*>(&h));
}

// ---------------- merged prep kernel ----------------
__global__ void prep_all(const float* __restrict__ W0, const float* __restrict__ Ws,
                         const float* __restrict__ W1,
                         const float* __restrict__ bn_g, const float* __restrict__ bn_b,
                         const float* __restrict__ bn_m, const float* __restrict__ bn_v){
    int blk = blockIdx.x, tid = threadIdx.x;
    if (blk < 32){                                  // W0^T: 8192 entries (k<32 part)
        int i = blk * 256 + tid;
        int n = i >> 5, k = i & 31;
        g_w0t[n * 64 + k] = cvt1(W0[k * 256 + n]);
    } else if (blk < 800){                          // Ws^T: 3*65536
        int i = (blk - 32) * 256 + tid;
        int l = i >> 16, r = i & 65535;
        int n = r >> 8, k = r & 255;
        g_wst[l][n * 256 + k] = cvt1(Ws[l * 65536 + k * 256 + n]);
    } else if (blk < 2976){                         // W1^T: 512*1088 (pad k>=1056 -> 0)
        int i = (blk - 800) * 256 + tid;
        int n = i / 1088, k = i - n * 1088;
        g_w1t[i] = (k < 1056) ? cvt1(W1[k * 512 + n]) : (u8)0;
    } else {                                        // BN fold: 512
        int i = (blk - 2976) * 256 + tid;
        if (i < 512){
            float sc = bn_g[i] * rsqrtf(bn_v[i] + 1e-5f);
            g_sc[i] = sc;
            g_sh[i] = bn_b[i] - bn_m[i] * sc;
        }
    }
}

__global__ void xcvt(const float* __restrict__ obs){
    int q = blockIdx.x * 256 + threadIdx.x;         // ROWS*4
    int row = q >> 2, j = q & 3;
    int b = row >> 10, n = row & 1023;
    const float4* s = reinterpret_cast<const float4*>(obs + (size_t)b * NBSTRIDE + 1024 + n * 32 + j * 8);
    float4 a = s[0], c = s[1];
    u32 w0 = (u32)pk8(a.x, a.y) | ((u32)pk8(a.z, a.w) << 16);
    u32 w1 = (u32)pk8(c.x, c.y) | ((u32)pk8(c.z, c.w) << 16);
    *reinterpret_cast<uint2*>(g_hc + (size_t)row * MIDB + j * 8) = make_uint2(w0, w1);
}

// ---------------- persistent FP8 GEMM, dynamic tiles ----------------
// Tile 64x256, 256 thr, occ 2, 8 warps (wm=wid&1, wn=wid>>1), warp tile 32x64.
// K chunk = 64 fp8 (2 k32 mma steps). 3-stage cp.async. SMEM pitch 80B/row.
// Stage: A 64x80=5120 @0, B 256x80=20480 @5120 -> 25600; x3 = 76800.
// red @76800 (2KB), musd @78848 (512B). Total 79360.
#define SMTOT 79360
template<int KFULL, bool LN, bool AGG, int AW>
__global__ void __launch_bounds__(256, 2)
gemm_mma(const u8* __restrict__ A, const u8* __restrict__ Bt, int slot, int ntiles,
         const float* __restrict__ bias, const float* __restrict__ gamma,
         const float* __restrict__ beta, u8* __restrict__ outp)
{
    extern __shared__ char sm[];
    __shared__ u32 s_tile;
    const u32 sb = s2u(sm);
    const int tid  = threadIdx.x;
    const int lane = tid & 31, wid = tid >> 5;
    const int wm = wid & 1, wn = wid >> 1;
    constexpr int NC = KFULL / 64;

    const int ar = tid >> 2, aseg = tid & 3;        // A loader: 64 rows x 4 segs

    for (;;){
        __syncthreads();
        if (tid == 0) s_tile = atomicAdd(&g_ctr[slot], 1u);
        __syncthreads();
        const u32 t = s_tile;
        if (t >= (u32)ntiles) break;

        const int row0  = LN ? ((int)t << 6) : ((int)(t >> 1) << 6);
        const int ncol0 = LN ? 0 : ((int)(t & 1) << 8);
        const u8* Bp = Bt + (size_t)ncol0 * KFULL;

        const int arow = row0 + ar;
        const int an = arow & 1023, agr = an >> 5, agc = an & 31;

        auto load_chunk = [&](int kc, int stg){
            const u32 stgo = (u32)stg * 25600u;
            {   // A
                const u32 aoff = stgo + (u32)(ar * 80 + aseg * 16);
                const int colb = kc * 64 + aseg * 16;
                if (AGG){
                    if (AW != 256 && colb >= AW){
                        *reinterpret_cast<uint4*>(sm + aoff) = make_uint4(0u, 0u, 0u, 0u);
                    } else {
                        const u8* base = A + (size_t)arow * MIDB + colb;
                        float s[16];
#pragma unroll
                        for (int e = 0; e < 16; e++) s[e] = 0.f;
                        if (agc > 0)  addq(s, *reinterpret_cast<const uint4*>(base - MIDB));
                        if (agc < 31) addq(s, *reinterpret_cast<const uint4*>(base + MIDB));
                        if (agr > 0)  addq(s, *reinterpret_cast<const uint4*>(base - 32 * MIDB));
                        if (agr < 31) addq(s, *reinterpret_cast<const uint4*>(base + 32 * MIDB));
                        u32 w0 = (u32)pk8(s[0],  s[1])  | ((u32)pk8(s[2],  s[3])  << 16);
                        u32 w1 = (u32)pk8(s[4],  s[5])  | ((u32)pk8(s[6],  s[7])  << 16);
                        u32 w2 = (u32)pk8(s[8],  s[9])  | ((u32)pk8(s[10], s[11]) << 16);
                        u32 w3 = (u32)pk8(s[12], s[13]) | ((u32)pk8(s[14], s[15]) << 16);
                        *reinterpret_cast<uint4*>(sm + aoff) = make_uint4(w0, w1, w2, w3);
                    }
                } else {
                    cpa16(sb + aoff, A + (size_t)arow * MIDB + colb);
                }
            }
#pragma unroll
            for (int i = 0; i < 4; i++){            // B: 256 rows x 4 segs
                int q = tid + 256 * i;
                int n = q >> 2, seg = q & 3;
                cpa16(sb + stgo + 5120u + (u32)(n * 80 + seg * 16),
                      Bp + (size_t)n * KFULL + kc * 64 + seg * 16);
            }
        };

        u32 acc[2][8][2];
#pragma unroll
        for (int mt = 0; mt < 2; mt++)
#pragma unroll
            for (int nt = 0; nt < 8; nt++){ acc[mt][nt][0] = 0u; acc[mt][nt][1] = 0u; }

#pragma unroll
        for (int p = 0; p < 2; p++){
            if (p < NC) load_chunk(p, p);
            CP_COMMIT();
        }

        for (int kc = 0; kc < NC; kc++){
            CP_WAIT(1);
            __syncthreads();
            if (kc + 2 < NC) load_chunk(kc + 2, (kc + 2) % 3);
            CP_COMMIT();

            const u32 Ab = sb + (u32)(kc % 3) * 25600u;
            const u32 Bb = Ab + 5120u;
#pragma unroll
            for (int s = 0; s < 2; s++){
                u32 a[2][4], b[8][2];
#pragma unroll
                for (int mt = 0; mt < 2; mt++){
                    u32 addr = Ab + (u32)((wm * 32 + mt * 16 + (lane & 7) + ((lane >> 3) & 1) * 8) * 80
                                          + s * 32 + (lane >> 4) * 16);
                    LDSM4(a[mt][0], a[mt][1], a[mt][2], a[mt][3], addr);
                }
#pragma unroll
                for (int np = 0; np < 4; np++){
                    u32 addr = Bb + (u32)((wn * 64 + (np * 2 + (lane >> 4)) * 8 + (lane & 7)) * 80
                                          + s * 32 + ((lane >> 3) & 1) * 16);
                    LDSM4(b[np * 2][0], b[np * 2][1], b[np * 2 + 1][0], b[np * 2 + 1][1], addr);
                }
#pragma unroll
                for (int mt = 0; mt < 2; mt++)
#pragma unroll
                    for (int nt = 0; nt < 8; nt++)
                        mma_fp8_h(acc[mt][nt], a[mt], b[nt]);
            }
        }
        __syncthreads();

        const int cbase = wn * 64 + (lane & 3) * 2;

        if (LN){
            float vf[2][8][4];
            float s1[2][2] = {{0,0},{0,0}}, s2[2][2] = {{0,0},{0,0}};
#pragma unroll
            for (int mt = 0; mt < 2; mt++)
#pragma unroll
                for (int nt = 0; nt < 8; nt++){
                    int c = cbase + nt * 8;
                    float b0 = __ldg(bias + c), b1v = __ldg(bias + c + 1);
                    float2 p0 = h2f(acc[mt][nt][0]);
                    float2 p1 = h2f(acc[mt][nt][1]);
                    float v0 = p0.x + b0, v1 = p0.y + b1v;
                    float v2 = p1.x + b0, v3 = p1.y + b1v;
                    vf[mt][nt][0] = v0; vf[mt][nt][1] = v1;
                    vf[mt][nt][2] = v2; vf[mt][nt][3] = v3;
                    s1[mt][0] += v0 + v1; s2[mt][0] = fmaf(v0, v0, fmaf(v1, v1, s2[mt][0]));
                    s1[mt][1] += v2 + v3; s2[mt][1] = fmaf(v2, v2, fmaf(v3, v3, s2[mt][1]));
                }
#pragma unroll
            for (int o = 1; o <= 2; o <<= 1)
#pragma unroll
                for (int mt = 0; mt < 2; mt++)
#pragma unroll
                    for (int h = 0; h < 2; h++){
                        s1[mt][h] += __shfl_xor_sync(0xffffffffu, s1[mt][h], o);
                        s2[mt][h] += __shfl_xor_sync(0xffffffffu, s2[mt][h], o);
                    }
            float2* red = reinterpret_cast<float2*>(sm + 76800);
            if ((lane & 3) == 0){
#pragma unroll
                for (int mt = 0; mt < 2; mt++)
#pragma unroll
                    for (int h = 0; h < 2; h++){
                        int r = wm * 32 + mt * 16 + (lane >> 2) + 8 * h;
                        red[r * 4 + wn] = make_float2(s1[mt][h], s2[mt][h]);
                    }
            }
            __syncthreads();
            float2* musd = reinterpret_cast<float2*>(sm + 78848);
            if (tid < 64){
                float S1 = 0.f, S2 = 0.f;
#pragma unroll
                for (int w = 0; w < 4; w++){ float2 v = red[tid * 4 + w]; S1 += v.x; S2 += v.y; }
                float mu = S1 * (1.f / 256.f);
                float rstd = rsqrtf(fmaf(-mu, mu, S2 * (1.f / 256.f)) + 1e-5f);
                musd[tid] = make_float2(mu, rstd);
            }
            __syncthreads();
#pragma unroll
            for (int mt = 0; mt < 2; mt++)
#pragma unroll
                for (int h = 0; h < 2; h++){
                    int r = wm * 32 + mt * 16 + (lane >> 2) + 8 * h;
                    float2 ms = musd[r];
                    u8* orow = outp + (size_t)(row0 + r) * MIDB;
#pragma unroll
                    for (int nt = 0; nt < 8; nt++){
                        int c = cbase + nt * 8;
                        float v0 = vf[mt][nt][2 * h], v1 = vf[mt][nt][2 * h + 1];
                        float o0 = fmaxf(fmaf((v0 - ms.x) * ms.y, __ldg(gamma + c),     __ldg(beta + c)),     0.f);
                        float o1 = fmaxf(fmaf((v1 - ms.x) * ms.y, __ldg(gamma + c + 1), __ldg(beta + c + 1)), 0.f);
                        *reinterpret_cast<u16*>(orow + c) = pk8(o0, o1);
                    }
                }
        } else {
            // HEAD: bias -> BN -> ReLU -> dot(W2 slice) -> per-row partial
            float* part = reinterpret_cast<float*>(sm + 76800);   // [64][4]
#pragma unroll
            for (int mt = 0; mt < 2; mt++)
#pragma unroll
                for (int h = 0; h < 2; h++){
                    int r = wm * 32 + mt * 16 + (lane >> 2) + 8 * h;
                    float s = 0.f;
#pragma unroll
                    for (int nt = 0; nt < 8; nt++){
                        int c  = cbase + nt * 8;
                        int gc = ncol0 + c;
                        float2 p = (h == 0) ? h2f(acc[mt][nt][0]) : h2f(acc[mt][nt][1]);
                        float v0 = p.x + __ldg(bias + gc);
                        float v1 = p.y + __ldg(bias + gc + 1);
                        float t0 = fmaxf(fmaf(v0, g_sc[gc],     g_sh[gc]),     0.f);
                        float t1 = fmaxf(fmaf(v1, g_sc[gc + 1], g_sh[gc + 1]), 0.f);
                        s = fmaf(t0, __ldg(gamma + gc), s);
                        s = fmaf(t1, __ldg(gamma + gc + 1), s);
                    }
                    s += __shfl_xor_sync(0xffffffffu, s, 1);
                    s += __shfl_xor_sync(0xffffffffu, s, 2);
                    if ((lane & 3) == 0) part[r * 4 + wn] = s;
                }
            __syncthreads();
            if (tid < 64){
                float S = part[tid * 4] + part[tid * 4 + 1] + part[tid * 4 + 2] + part[tid * 4 + 3];
                g_part[(size_t)(t & 1) * ROWS + row0 + tid] = S;
            }
        }
    }
}

// ---------------- tail: combine partials, +b2, mask; reset counters ----------------
__global__ void mask_kernel(const float* __restrict__ obs, const float* __restrict__ b2,
                            float* __restrict__ out){
    int idx = blockIdx.x * 256 + threadIdx.x;           // 65536
    int b = idx >> 10, n = idx & 1023;
    float y = g_part[idx] + g_part[ROWS + idx] + b2[0];
    out[idx] = (obs[(size_t)b * NBSTRIDE + n] != 0.f) ? y : MIN_VAL;
    if (idx < 8) g_ctr[idx] = 0u;                       // reset for next graph replay
}

// ---------------- launch ----------------
extern "C" void kernel_launch(void* const* d_in, const int* in_sizes, int n_in,
                              void* d_out, int out_size) {
    const float* obs  = (const float*)d_in[0];
    const float* W0   = (const float*)d_in[3];
    const float* b0   = (const float*)d_in[4];
    const float* g0   = (const float*)d_in[5];
    const float* be0  = (const float*)d_in[6];
    const float* Ws   = (const float*)d_in[7];
    const float* bs   = (const float*)d_in[8];
    const float* gs   = (const float*)d_in[9];
    const float* bes  = (const float*)d_in[10];
    const float* W1   = (const float*)d_in[11];
    const float* b1   = (const float*)d_in[12];
    const float* bn_g = (const float*)d_in[13];
    const float* bn_b = (const float*)d_in[14];
    const float* bn_m = (const float*)d_in[15];
    const float* bn_v = (const float*)d_in[16];
    const float* W2   = (const float*)d_in[17];
    const float* b2   = (const float*)d_in[18];
    float* out = (float*)d_out;

    u8 *hc, *w0t, *wst, *w1t;
    cudaGetSymbolAddress((void**)&hc,  g_hc);
    cudaGetSymbolAddress((void**)&w0t, g_w0t);
    cudaGetSymbolAddress((void**)&wst, g_wst);
    cudaGetSymbolAddress((void**)&w1t, g_w1t);

    cudaFuncSetAttribute(gemm_mma<64,   true,  true,  32 >, cudaFuncAttributeMaxDynamicSharedMemorySize, SMTOT);
    cudaFuncSetAttribute(gemm_mma<256,  true,  true,  256>, cudaFuncAttributeMaxDynamicSharedMemorySize, SMTOT);
    cudaFuncSetAttribute(gemm_mma<1088, false, false, 256>, cudaFuncAttributeMaxDynamicSharedMemorySize, SMTOT);

    prep_all<<<2978, 256>>>(W0, Ws, W1, bn_g, bn_b, bn_m, bn_v);
    xcvt<<<1024, 256>>>(obs);

    // Layer 0: h1 = relu(LN(agg(x) @ W0 + b0))
    gemm_mma<64, true, true, 32><<<GRID_P, 256, SMTOT>>>(
        hc, w0t, 0, 1024, b0, g0, be0, hc + 32);

    // Layers 1..3
    for (int l = 1; l < 4; l++) {
        gemm_mma<256, true, true, 256><<<GRID_P, 256, SMTOT>>>(
            hc + 32 + (l - 1) * 256, wst + (size_t)(l - 1) * 65536, l, 1024,
            bs + (l - 1) * 256, gs + (l - 1) * 256, bes + (l - 1) * 256,
            hc + 32 + l * 256);
    }

    // Head: fused GEMM + BN + ReLU + W2-dot -> g_part (2048 tiles: 1024 M x 2 N-halves)
    gemm_mma<1088, false, false, 256><<<GRID_P, 256, SMTOT>>>(
        hc, w1t, 4, 2048, b1, W2, nullptr, nullptr);

    // Tail: combine + mask + counter reset
    mask_kernel<<<256, 256>>>(obs, b2, out);
}

// round 11
// speedup vs baseline: 6.8015x; 1.0354x over previous
#include <cuda_runtime.h>
#include <cuda_bf16.h>
#include <cuda_fp16.h>

typedef unsigned int u32;
typedef unsigned char u8;
typedef unsigned short u16;

#define ROWS 65536
#define NBSTRIDE 33792
#define MIDB 1088              // padded concat stride (1056 data + 32 zeros)
#define MIN_VAL (-10000000.0f)
#define GRID_P 304

// ---------------- persistent scratch (BSS, zero-init) ----------------
__device__ u8    g_hc [(size_t)ROWS * MIDB];   // fp8: [x(32) | h1..h4(256 ea) | zeros(32)]
__device__ u8    g_w0t[256 * 64];              // W0^T [N=256][K=64], k>=32 zero
__device__ u8    g_wst[3][256 * 256];          // Ws^T fp8
__device__ u8    g_w1t[(size_t)512 * 1088];    // W1^T fp8, k>=1056 zero
__device__ float g_part[2 * ROWS];             // head partial dots per N-half
__device__ float g_sc[512], g_sh[512];         // folded BN scale/shift
__device__ u32   g_ctr[8];                     // dynamic tile counters

// ---------------- helpers ----------------
__device__ __forceinline__ u32 s2u(const void* p){
    u32 a;
    asm("{ .reg .u64 t; cvta.to.shared.u64 t, %1; cvt.u32.u64 %0, t; }" : "=r"(a) : "l"(p));
    return a;
}
__device__ __forceinline__ void cpa16(u32 dst, const void* src){
    asm volatile("cp.async.cg.shared.global [%0], [%1], 16;" :: "r"(dst), "l"(src));
}
#define CP_COMMIT() asm volatile("cp.async.commit_group;" ::: "memory")
#define CP_WAIT(n)  asm volatile("cp.async.wait_group %0;" :: "n"(n) : "memory")

__device__ __forceinline__ void mma_fp8_h(u32* c, const u32* a, const u32* b){
    asm volatile("mma.sync.aligned.m16n8k32.row.col.f16.e4m3.e4m3.f16 "
        "{%0,%1}, {%2,%3,%4,%5}, {%6,%7}, {%0,%1};"
        : "+r"(c[0]), "+r"(c[1])
        : "r"(a[0]), "r"(a[1]), "r"(a[2]), "r"(a[3]), "r"(b[0]), "r"(b[1]));
}
#define LDSM4(r0, r1, r2, r3, addr) \
    asm volatile("ldmatrix.sync.aligned.m8n8.x4.shared.b16 {%0,%1,%2,%3}, [%4];" \
        : "=r"(r0), "=r"(r1), "=r"(r2), "=r"(r3) : "r"(addr))

__device__ __forceinline__ u16 pk8(float lo, float hi){
    u16 t;
    asm("cvt.rn.satfinite.e4m3x2.f32 %0, %1, %2;" : "=h"(t) : "f"(hi), "f"(lo));
    return t;
}
__device__ __forceinline__ u8 cvt1(float v){ return (u8)(pk8(v, 0.f) & 0xff); }
__device__ __forceinline__ float2 h2f(u32 h){
    return __half22float2(*reinterpret_cast<__half2*>(&h));
}
// f16x2 accumulate of 4 packed e4m3 into two f16x2 accumulators
__device__ __forceinline__ void hacc_fp8x4(u32& a0, u32& a1, u32 v){
    u32 f0, f1;
    asm("cvt.rn.f16x2.e4m3x2 %0, %1;" : "=r"(f0) : "h"((u16)(v & 0xffff)));
    asm("cvt.rn.f16x2.e4m3x2 %0, %1;" : "=r"(f1) : "h"((u16)(v >> 16)));
    asm("add.rn.f16x2 %0, %0, %1;" : "+r"(a0) : "r"(f0));
    asm("add.rn.f16x2 %0, %0, %1;" : "+r"(a1) : "r"(f1));
}
__device__ __forceinline__ u32 pack2h(u32 h0, u32 h1){
    u16 a, b;
    asm("cvt.rn.satfinite.e4m3x2.f16x2 %0, %1;" : "=h"(a) : "r"(h0));
    asm("cvt.rn.satfinite.e4m3x2.f16x2 %0, %1;" : "=h"(b) : "r"(h1));
    return (u32)a | ((u32)b << 16);
}

// ---------------- merged prep kernel ----------------
__global__ void prep_all(const float* __restrict__ W0, const float* __restrict__ Ws,
                         const float* __restrict__ W1,
                         const float* __restrict__ bn_g, const float* __restrict__ bn_b,
                         const float* __restrict__ bn_m, const float* __restrict__ bn_v){
    int blk = blockIdx.x, tid = threadIdx.x;
    if (blk < 32){
        int i = blk * 256 + tid;
        int n = i >> 5, k = i & 31;
        g_w0t[n * 64 + k] = cvt1(W0[k * 256 + n]);
    } else if (blk < 800){
        int i = (blk - 32) * 256 + tid;
        int l = i >> 16, r = i & 65535;
        int n = r >> 8, k = r & 255;
        g_wst[l][n * 256 + k] = cvt1(Ws[l * 65536 + k * 256 + n]);
    } else if (blk < 2976){
        int i = (blk - 800) * 256 + tid;
        int n = i / 1088, k = i - n * 1088;
        g_w1t[i] = (k < 1056) ? cvt1(W1[k * 512 + n]) : (u8)0;
    } else {
        int i = (blk - 2976) * 256 + tid;
        if (i < 512){
            float sc = bn_g[i] * rsqrtf(bn_v[i] + 1e-5f);
            g_sc[i] = sc;
            g_sh[i] = bn_b[i] - bn_m[i] * sc;
        }
    }
}

__global__ void xcvt(const float* __restrict__ obs){
    int q = blockIdx.x * 256 + threadIdx.x;
    int row = q >> 2, j = q & 3;
    int b = row >> 10, n = row & 1023;
    const float4* s = reinterpret_cast<const float4*>(obs + (size_t)b * NBSTRIDE + 1024 + n * 32 + j * 8);
    float4 a = s[0], c = s[1];
    u32 w0 = (u32)pk8(a.x, a.y) | ((u32)pk8(a.z, a.w) << 16);
    u32 w1 = (u32)pk8(c.x, c.y) | ((u32)pk8(c.z, c.w) << 16);
    *reinterpret_cast<uint2*>(g_hc + (size_t)row * MIDB + j * 8) = make_uint2(w0, w1);
}

// ---------------- persistent FP8 GEMM, dynamic tiles, pipelined fused agg ----------------
// Tile 64x256, 256 thr, occ 2, 8 warps (wm=wid&1, wn=wid>>1), warp tile 32x64.
// K chunk = 64 fp8 (2 k32 mma). 3-stage. Stage: A 64x80 @0 (5120), B 256x80 @5120 (20480) = 25600.
// red @76800, musd @78848. Total 79360.
#define SMTOT 79360
template<int KFULL, bool LN, bool AGG, int AW>
__global__ void __launch_bounds__(256, 2)
gemm_mma(const u8* __restrict__ A, const u8* __restrict__ Bt, int slot, int ntiles,
         const float* __restrict__ bias, const float* __restrict__ gamma,
         const float* __restrict__ beta, u8* __restrict__ outp)
{
    extern __shared__ char sm[];
    __shared__ u32 s_tile;
    const u32 sb = s2u(sm);
    const int tid  = threadIdx.x;
    const int lane = tid & 31, wid = tid >> 5;
    const int wm = wid & 1, wn = wid >> 1;
    constexpr int NC = KFULL / 64;

    const int ar = tid >> 2, aseg = tid & 3;        // A loader: 64 rows x 4 segs

    for (;;){
        __syncthreads();
        if (tid == 0) s_tile = atomicAdd(&g_ctr[slot], 1u);
        __syncthreads();
        const u32 t = s_tile;
        if (t >= (u32)ntiles) break;

        const int row0  = LN ? ((int)t << 6) : ((int)(t >> 1) << 6);
        const int ncol0 = LN ? 0 : ((int)(t & 1) << 8);
        const u8* Bp = Bt + (size_t)ncol0 * KFULL;

        const int arow = row0 + ar;
        const int an = arow & 1023, agr = an >> 5, agc = an & 31;

        // --- A neighbor LDG into regs (non-blocking until use) ---
        auto ldgA = [&](int kc, uint4* r){
            const int colb = kc * 64 + aseg * 16;
            r[0] = r[1] = r[2] = r[3] = make_uint4(0u, 0u, 0u, 0u);
            if (AW == 256 || colb < AW){
                const u8* base = A + (size_t)arow * MIDB + colb;
                if (agc > 0)  r[0] = *reinterpret_cast<const uint4*>(base - MIDB);
                if (agc < 31) r[1] = *reinterpret_cast<const uint4*>(base + MIDB);
                if (agr > 0)  r[2] = *reinterpret_cast<const uint4*>(base - 32 * MIDB);
                if (agr < 31) r[3] = *reinterpret_cast<const uint4*>(base + 32 * MIDB);
            }
        };
        // --- f16x2 sum + e4m3 repack + STS ---
        auto stsA = [&](int stg, const uint4* r){
            u32 s[8];
#pragma unroll
            for (int e = 0; e < 8; e++) s[e] = 0u;
#pragma unroll
            for (int j = 0; j < 4; j++){
                hacc_fp8x4(s[0], s[1], r[j].x);
                hacc_fp8x4(s[2], s[3], r[j].y);
                hacc_fp8x4(s[4], s[5], r[j].z);
                hacc_fp8x4(s[6], s[7], r[j].w);
            }
            *reinterpret_cast<uint4*>(sm + (u32)stg * 25600u + (u32)(ar * 80 + aseg * 16)) =
                make_uint4(pack2h(s[0], s[1]), pack2h(s[2], s[3]),
                           pack2h(s[4], s[5]), pack2h(s[6], s[7]));
        };
        auto cpA = [&](int kc, int stg){
            cpa16(sb + (u32)stg * 25600u + (u32)(ar * 80 + aseg * 16),
                  A + (size_t)arow * MIDB + kc * 64 + aseg * 16);
        };
        auto cpB = [&](int kc, int stg){
#pragma unroll
            for (int i = 0; i < 4; i++){
                int q = tid + 256 * i;
                int n = q >> 2, seg = q & 3;
                cpa16(sb + (u32)stg * 25600u + 5120u + (u32)(n * 80 + seg * 16),
                      Bp + (size_t)n * KFULL + kc * 64 + seg * 16);
            }
        };

        u32 acc[2][8][2];
#pragma unroll
        for (int mt = 0; mt < 2; mt++)
#pragma unroll
            for (int nt = 0; nt < 8; nt++){ acc[mt][nt][0] = 0u; acc[mt][nt][1] = 0u; }

        uint4 ra[4];
        // prologue: always 2 committed groups
#pragma unroll
        for (int p = 0; p < 2; p++){
            if (p < NC){
                if (AGG){ ldgA(p, ra); stsA(p, ra); }
                else    cpA(p, p);
                cpB(p, p);
            }
            CP_COMMIT();
        }

        for (int kc = 0; kc < NC; kc++){
            const bool pre = (kc + 2 < NC);
            const int stg2 = (kc + 2) % 3;
            if (pre){
                if (AGG) ldgA(kc + 2, ra);     // issue LDGs early; consumed after mma
                else     cpA(kc + 2, stg2);
                cpB(kc + 2, stg2);
            }
            CP_COMMIT();
            CP_WAIT(2);
            __syncthreads();

            const u32 Ab = sb + (u32)(kc % 3) * 25600u;
            const u32 Bb = Ab + 5120u;
#pragma unroll
            for (int s = 0; s < 2; s++){
                u32 a[2][4], b[8][2];
#pragma unroll
                for (int mt = 0; mt < 2; mt++){
                    u32 addr = Ab + (u32)((wm * 32 + mt * 16 + (lane & 7) + ((lane >> 3) & 1) * 8) * 80
                                          + s * 32 + (lane >> 4) * 16);
                    LDSM4(a[mt][0], a[mt][1], a[mt][2], a[mt][3], addr);
                }
#pragma unroll
                for (int np = 0; np < 4; np++){
                    u32 addr = Bb + (u32)((wn * 64 + (np * 2 + (lane >> 4)) * 8 + (lane & 7)) * 80
                                          + s * 32 + ((lane >> 3) & 1) * 16);
                    LDSM4(b[np * 2][0], b[np * 2][1], b[np * 2 + 1][0], b[np * 2 + 1][1], addr);
                }
#pragma unroll
                for (int mt = 0; mt < 2; mt++)
#pragma unroll
                    for (int nt = 0; nt < 8; nt++)
                        mma_fp8_h(acc[mt][nt], a[mt], b[nt]);
            }
            if (AGG && pre) stsA(stg2, ra);    // convert + STS after mma hides LDG latency
        }
        __syncthreads();

        const int cbase = wn * 64 + (lane & 3) * 2;

        if (LN){
            float vf[2][8][4];
            float s1[2][2] = {{0,0},{0,0}}, s2[2][2] = {{0,0},{0,0}};
#pragma unroll
            for (int mt = 0; mt < 2; mt++)
#pragma unroll
                for (int nt = 0; nt < 8; nt++){
                    int c = cbase + nt * 8;
                    float b0 = __ldg(bias + c), b1v = __ldg(bias + c + 1);
                    float2 p0 = h2f(acc[mt][nt][0]);
                    float2 p1 = h2f(acc[mt][nt][1]);
                    float v0 = p0.x + b0, v1 = p0.y + b1v;
                    float v2 = p1.x + b0, v3 = p1.y + b1v;
                    vf[mt][nt][0] = v0; vf[mt][nt][1] = v1;
                    vf[mt][nt][2] = v2; vf[mt][nt][3] = v3;
                    s1[mt][0] += v0 + v1; s2[mt][0] = fmaf(v0, v0, fmaf(v1, v1, s2[mt][0]));
                    s1[mt][1] += v2 + v3; s2[mt][1] = fmaf(v2, v2, fmaf(v3, v3, s2[mt][1]));
                }
#pragma unroll
            for (int o = 1; o <= 2; o <<= 1)
#pragma unroll
                for (int mt = 0; mt < 2; mt++)
#pragma unroll
                    for (int h = 0; h < 2; h++){
                        s1[mt][h] += __shfl_xor_sync(0xffffffffu, s1[mt][h], o);
                        s2[mt][h] += __shfl_xor_sync(0xffffffffu, s2[mt][h], o);
                    }
            float2* red = reinterpret_cast<float2*>(sm + 76800);
            if ((lane & 3) == 0){
#pragma unroll
                for (int mt = 0; mt < 2; mt++)
#pragma unroll
                    for (int h = 0; h < 2; h++){
                        int r = wm * 32 + mt * 16 + (lane >> 2) + 8 * h;
                        red[r * 4 + wn] = make_float2(s1[mt][h], s2[mt][h]);
                    }
            }
            __syncthreads();
            float2* musd = reinterpret_cast<float2*>(sm + 78848);
            if (tid < 64){
                float S1 = 0.f, S2 = 0.f;
#pragma unroll
                for (int w = 0; w < 4; w++){ float2 v = red[tid * 4 + w]; S1 += v.x; S2 += v.y; }
                float mu = S1 * (1.f / 256.f);
                float rstd = rsqrtf(fmaf(-mu, mu, S2 * (1.f / 256.f)) + 1e-5f);
                musd[tid] = make_float2(mu, rstd);
            }
            __syncthreads();
#pragma unroll
            for (int mt = 0; mt < 2; mt++)
#pragma unroll
                for (int h = 0; h < 2; h++){
                    int r = wm * 32 + mt * 16 + (lane >> 2) + 8 * h;
                    float2 ms = musd[r];
                    u8* orow = outp + (size_t)(row0 + r) * MIDB;
#pragma unroll
                    for (int nt = 0; nt < 8; nt++){
                        int c = cbase + nt * 8;
                        float v0 = vf[mt][nt][2 * h], v1 = vf[mt][nt][2 * h + 1];
                        float o0 = fmaxf(fmaf((v0 - ms.x) * ms.y, __ldg(gamma + c),     __ldg(beta + c)),     0.f);
                        float o1 = fmaxf(fmaf((v1 - ms.x) * ms.y, __ldg(gamma + c + 1), __ldg(beta + c + 1)), 0.f);
                        *reinterpret_cast<u16*>(orow + c) = pk8(o0, o1);
                    }
                }
        } else {
            float* part = reinterpret_cast<float*>(sm + 76800);
#pragma unroll
            for (int mt = 0; mt < 2; mt++)
#pragma unroll
                for (int h = 0; h < 2; h++){
                    int r = wm * 32 + mt * 16 + (lane >> 2) + 8 * h;
                    float s = 0.f;
#pragma unroll
                    for (int nt = 0; nt < 8; nt++){
                        int c  = cbase + nt * 8;
                        int gc = ncol0 + c;
                        float2 p = (h == 0) ? h2f(acc[mt][nt][0]) : h2f(acc[mt][nt][1]);
                        float v0 = p.x + __ldg(bias + gc);
                        float v1 = p.y + __ldg(bias + gc + 1);
                        float t0 = fmaxf(fmaf(v0, g_sc[gc],     g_sh[gc]),     0.f);
                        float t1 = fmaxf(fmaf(v1, g_sc[gc + 1], g_sh[gc + 1]), 0.f);
                        s = fmaf(t0, __ldg(gamma + gc), s);
                        s = fmaf(t1, __ldg(gamma + gc + 1), s);
                    }
                    s += __shfl_xor_sync(0xffffffffu, s, 1);
                    s += __shfl_xor_sync(0xffffffffu, s, 2);
                    if ((lane & 3) == 0) part[r * 4 + wn] = s;
                }
            __syncthreads();
            if (tid < 64){
                float S = part[tid * 4] + part[tid * 4 + 1] + part[tid * 4 + 2] + part[tid * 4 + 3];
                g_part[(size_t)(t & 1) * ROWS + row0 + tid] = S;
            }
        }
    }
}

// ---------------- tail: combine partials, +b2, mask; reset counters ----------------
__global__ void mask_kernel(const float* __restrict__ obs, const float* __restrict__ b2,
                            float* __restrict__ out){
    int idx = blockIdx.x * 256 + threadIdx.x;
    int b = idx >> 10, n = idx & 1023;
    float y = g_part[idx] + g_part[ROWS + idx] + b2[0];
    out[idx] = (obs[(size_t)b * NBSTRIDE + n] != 0.f) ? y : MIN_VAL;
    if (idx < 8) g_ctr[idx] = 0u;
}

// ---------------- launch ----------------
extern "C" void kernel_launch(void* const* d_in, const int* in_sizes, int n_in,
                              void* d_out, int out_size) {
    const float* obs  = (const float*)d_in[0];
    const float* W0   = (const float*)d_in[3];
    const float* b0   = (const float*)d_in[4];
    const float* g0   = (const float*)d_in[5];
    const float* be0  = (const float*)d_in[6];
    const float* Ws   = (const float*)d_in[7];
    const float* bs   = (const float*)d_in[8];
    const float* gs   = (const float*)d_in[9];
    const float* bes  = (const float*)d_in[10];
    const float* W1   = (const float*)d_in[11];
    const float* b1   = (const float*)d_in[12];
    const float* bn_g = (const float*)d_in[13];
    const float* bn_b = (const float*)d_in[14];
    const float* bn_m = (const float*)d_in[15];
    const float* bn_v = (const float*)d_in[16];
    const float* W2   = (const float*)d_in[17];
    const float* b2   = (const float*)d_in[18];
    float* out = (float*)d_out;

    u8 *hc, *w0t, *wst, *w1t;
    cudaGetSymbolAddress((void**)&hc,  g_hc);
    cudaGetSymbolAddress((void**)&w0t, g_w0t);
    cudaGetSymbolAddress((void**)&wst, g_wst);
    cudaGetSymbolAddress((void**)&w1t, g_w1t);

    cudaFuncSetAttribute(gemm_mma<64,   true,  true,  32 >, cudaFuncAttributeMaxDynamicSharedMemorySize, SMTOT);
    cudaFuncSetAttribute(gemm_mma<256,  true,  true,  256>, cudaFuncAttributeMaxDynamicSharedMemorySize, SMTOT);
    cudaFuncSetAttribute(gemm_mma<1088, false, false, 256>, cudaFuncAttributeMaxDynamicSharedMemorySize, SMTOT);

    prep_all<<<2978, 256>>>(W0, Ws, W1, bn_g, bn_b, bn_m, bn_v);
    xcvt<<<1024, 256>>>(obs);

    gemm_mma<64, true, true, 32><<<GRID_P, 256, SMTOT>>>(
        hc, w0t, 0, 1024, b0, g0, be0, hc + 32);

    for (int l = 1; l < 4; l++) {
        gemm_mma<256, true, true, 256><<<GRID_P, 256, SMTOT>>>(
            hc + 32 + (l - 1) * 256, wst + (size_t)(l - 1) * 65536, l, 1024,
            bs + (l - 1) * 256, gs + (l - 1) * 256, bes + (l - 1) * 256,
            hc + 32 + l * 256);
    }

    gemm_mma<1088, false, false, 256><<<GRID_P, 256, SMTOT>>>(
        hc, w1t, 4, 2048, b1, W2, nullptr, nullptr);

    mask_kernel<<<256, 256>>>(obs, b2, out);
}